// round 15
// baseline (speedup 1.0000x reference)
#include <cuda_runtime.h>
#include <cuda_bf16.h>
#include <math.h>
#include <stdio.h>

// ---------------- problem constants ----------------
#define Bq   4
#define Sq   512
#define Nq   256
#define Eq   42
#define Pq   256
#define Kq   3
#define Lq   4
#define HBq  768
#define DTq  20
#define DIq  20
#define Gq   256
#define NLq  2
#define Rq   97
#define NHq  4
#define D0q  808          // HB+DT+DI
#define BANKq 1576        // D0 + G*(NL+1)
#define BANK2q 3152       // 2*BANK (abs|prod)
#define BANK4q 6304       // 4*BANK
#define BANK5q 7880       // 5*BANK
#define DHq  394          // BANK/NH
#define Mlstm (Bq*Pq*Kq)        // 3072
#define MlstmT (Mlstm*Lq)       // 12288
#define BPq  (Bq*Pq)            // 1024
#define NBANKROWS (Bq*Eq)       // 168 distinct entity-bank rows

typedef __nv_bfloat16 bf16;
typedef __nv_bfloat162 bf162;

// ---------------- scratch (static device memory; no allocations allowed) ----------------
__device__ float g_enc   [Bq*Sq*D0q];
__device__ float g_feats [Bq*Nq*BANKq];
__device__ float g_tmp   [Bq*Nq*D0q];
__device__ float g_x1    [Bq*Nq*Gq];
__device__ float g_xq    [Bq*Nq*Gq];
__device__ float g_xk    [Bq*Nq*Gq];
__device__ float g_xv    [Bq*Nq*Gq];
__device__ float g_att   [Bq*Nq*Nq];
__device__ float g_ih    [(size_t)MlstmT*BANK4q];   // t-major
__device__ float g_hh    [(size_t)Mlstm*BANK4q];
__device__ float g_c     [Mlstm*BANKq];
__device__ float g_hs1   [MlstmT*BANKq];            // t-major, compacted rows
__device__ float g_hf    [BPq*BANKq];
__device__ float g_tf    [BPq*BANKq];
__device__ float g_q     [BPq*BANKq];               // qb (side stream)
__device__ float g_ccand [BPq*BANKq];               // candidate c scratch
__device__ float g_k     [Mlstm*BANKq];
__device__ float g_v     [Mlstm*BANKq];
__device__ float g_pinfo [BPq*BANKq];
__device__ float g_pp    [2*(size_t)NBANKROWS*BANK5q]; // pred partials p1/p2
__device__ float g_p3    [(size_t)BPq*BANK5q];      // pred partial from abs/prod segs
__device__ int   g_validany[BPq];
__device__ float g_hid   [BPq*BANK5q];              // also proj scratch

// length-compaction state
__device__ int g_perm[Mlstm];
__device__ int g_iperm[Mlstm];
__device__ int g_cnt[4];

// bf16 split scratch
__device__ bf16 g_ah  [(size_t)MlstmT*BANKq];       // layer-0 seq; later pe
__device__ bf16 g_al  [(size_t)MlstmT*BANKq];
__device__ bf16 g_sh  [(size_t)Mlstm*BANKq];
__device__ bf16 g_sl  [(size_t)Mlstm*BANKq];
__device__ bf16 g_hch [(size_t)BPq*BANKq];          // candidate h
__device__ bf16 g_hcl [(size_t)BPq*BANKq];
__device__ bf16 g_q2h [(size_t)BPq*BANKq];          // query split (side stream)
__device__ bf16 g_q2l [(size_t)BPq*BANKq];
__device__ bf16 g_bkh [(size_t)NBANKROWS*BANKq];    // bank split (side stream)
__device__ bf16 g_bkl [(size_t)NBANKROWS*BANKq];
__device__ bf16 g_oph [(size_t)BPq*BANK2q];         // of abs/prod split (side stream)
__device__ bf16 g_opl [(size_t)BPq*BANK2q];
__device__ bf16 g_w1h [(size_t)BANK4q*BANKq];       // Wih0
__device__ bf16 g_w1l [(size_t)BANK4q*BANKq];
__device__ bf16 g_w2h [(size_t)BANK4q*BANKq];       // Whh0
__device__ bf16 g_w2l [(size_t)BANK4q*BANKq];
__device__ bf16 g_w3h [(size_t)BANK4q*BANKq];       // Wih1
__device__ bf16 g_w3l [(size_t)BANK4q*BANKq];
__device__ bf16 g_w4h [(size_t)BANK4q*BANKq];       // Whh1
__device__ bf16 g_w4l [(size_t)BANK4q*BANKq];
__device__ bf16 g_mwh [3*(size_t)BANKq*BANKq];      // mha_inW
__device__ bf16 g_mwl [3*(size_t)BANKq*BANKq];
__device__ bf16 g_owh [(size_t)BANKq*BANKq];        // mha_outW
__device__ bf16 g_owl [(size_t)BANKq*BANKq];
__device__ bf16 g_wph [(size_t)BANK5q*BANK5q];
__device__ bf16 g_wpl [(size_t)BANK5q*BANK5q];

// ================= fp32 tiled GEMM (small GCN ops + head) =================
template <bool TRANSB>
__global__ void __launch_bounds__(256)
gemm32_kernel(const float* __restrict__ A, const float* __restrict__ B,
              const float* __restrict__ bias, const float* __restrict__ resid,
              float* __restrict__ C,
              int M, int N, int K,
              int lda, int ldb, int ldc, int ldr,
              long sA, long sB, long sC, long sR,
              float alpha, int act)
{
    int bz = blockIdx.z;
    A += bz * sA; B += bz * sB; C += bz * sC;
    if (resid) resid += bz * sR;

    int row0 = blockIdx.y * 32;
    int col0 = blockIdx.x * 32;

    __shared__ float As[32][33];
    __shared__ float Bs[32][33];

    int tid = threadIdx.x;
    int tx = tid & 15, ty = tid >> 4;

    float acc[2][2] = {{0.f, 0.f}, {0.f, 0.f}};

    for (int k0 = 0; k0 < K; k0 += 32) {
#pragma unroll
        for (int l = 0; l < 4; l++) {
            int idx = tid + l * 256;
            int m = idx >> 5, kk = idx & 31;
            int gr = row0 + m, gk = k0 + kk;
            As[kk][m] = (gr < M && gk < K) ? A[(long)gr * lda + gk] : 0.f;
        }
#pragma unroll
        for (int l = 0; l < 4; l++) {
            int idx = tid + l * 256;
            if (TRANSB) {
                int n = idx >> 5, kk = idx & 31;
                int gn = col0 + n, gk = k0 + kk;
                Bs[kk][n] = (gn < N && gk < K) ? B[(long)gn * ldb + gk] : 0.f;
            } else {
                int kk = idx >> 5, n = idx & 31;
                int gn = col0 + n, gk = k0 + kk;
                Bs[kk][n] = (gn < N && gk < K) ? B[(long)gk * ldb + gn] : 0.f;
            }
        }
        __syncthreads();
#pragma unroll
        for (int kk = 0; kk < 32; kk++) {
            float a0 = As[kk][ty], a1 = As[kk][ty + 16];
            float b0 = Bs[kk][tx], b1 = Bs[kk][tx + 16];
            acc[0][0] = fmaf(a0, b0, acc[0][0]);
            acc[0][1] = fmaf(a0, b1, acc[0][1]);
            acc[1][0] = fmaf(a1, b0, acc[1][0]);
            acc[1][1] = fmaf(a1, b1, acc[1][1]);
        }
        __syncthreads();
    }

#pragma unroll
    for (int i = 0; i < 2; i++) {
        int r = row0 + ty + 16 * i;
        if (r >= M) continue;
#pragma unroll
        for (int j = 0; j < 2; j++) {
            int cc = col0 + tx + 16 * j;
            if (cc >= N) continue;
            float v = acc[i][j] * alpha;
            if (bias) v += bias[cc];
            if (act == 1) v = fmaxf(v, 0.f);
            if (resid) v += resid[(long)r * ldr + cc];
            C[(long)r * ldc + cc] = v;
        }
    }
}

static void gemm(bool transB,
                 const float* A, const float* B, const float* bias, const float* resid, float* C,
                 int M, int N, int K, int lda, int ldb, int ldc, int ldr,
                 long sA, long sB, long sC, long sR, int batch, float alpha, int act,
                 cudaStream_t st = 0)
{
    dim3 grid((N + 31) / 32, (M + 31) / 32, batch);
    if (transB)
        gemm32_kernel<true><<<grid, 256, 0, st>>>(A, B, bias, resid, C, M, N, K, lda, ldb, ldc, ldr, sA, sB, sC, sR, alpha, act);
    else
        gemm32_kernel<false><<<grid, 256, 0, st>>>(A, B, bias, resid, C, M, N, K, lda, ldb, ldc, ldr, sA, sB, sC, sR, alpha, act);
}

// ================= bf16 split-precision tensor-core GEMM (R6 loop + Mdev + ld) =================
#define LDSB 40
#define GSTG 3
#define PLANE_E (128*LDSB)
#define PLANE_B (PLANE_E*2)
#define STAGE_B (4*PLANE_B)

#define MMA_BF16(d, a, b) asm volatile( \
    "mma.sync.aligned.m16n8k16.row.col.f32.bf16.bf16.f32 " \
    "{%0,%1,%2,%3}, {%4,%5,%6,%7}, {%8,%9}, {%0,%1,%2,%3};" \
    : "+f"((d)[0]), "+f"((d)[1]), "+f"((d)[2]), "+f"((d)[3]) \
    : "r"((a)[0]), "r"((a)[1]), "r"((a)[2]), "r"((a)[3]), "r"((b)[0]), "r"((b)[1]))

#define LDSM4(r, addr) asm volatile( \
    "ldmatrix.sync.aligned.m8n8.x4.shared.b16 {%0,%1,%2,%3}, [%4];" \
    : "=r"((r)[0]), "=r"((r)[1]), "=r"((r)[2]), "=r"((r)[3]) : "r"(addr))

__device__ __forceinline__ void cpasync16(unsigned saddr, const void* g, int srcbytes)
{
    asm volatile("cp.async.cg.shared.global [%0], [%1], 16, %2;\n"
                 :: "r"(saddr), "l"(g), "r"(srcbytes));
}

__device__ __forceinline__ void gbf_prefetch(
    const bf16* __restrict__ Ah, const bf16* __restrict__ Al,
    const bf16* __restrict__ Bh, const bf16* __restrict__ Bl,
    long row0, long col0, int M, int N, int K, int ldA, int ldB,
    int kt, int T, unsigned sbase, int stg, int tid)
{
    if (kt >= T) return;
    long k0 = (long)kt * 32;
    unsigned sst = sbase + (unsigned)stg * STAGE_B;
#pragma unroll
    for (int i = 0; i < 2; i++) {
        int c = tid + i * 256;
        int r = c >> 2;
        int ko = (c & 3) * 8;
        long gk = k0 + ko;
        bool kok = gk < K;
        long gkc = kok ? gk : 0;
        unsigned soff = (unsigned)((r * LDSB + ko) * 2);
        {
            long gr = row0 + r;
            bool ok = kok && (gr < M);
            long grc = ok ? gr : 0;
            int nb = ok ? 16 : 0;
            cpasync16(sst + soff,            Ah + grc * ldA + gkc, nb);
            cpasync16(sst + PLANE_B + soff,  Al + grc * ldA + gkc, nb);
        }
        {
            long gn = col0 + r;
            bool ok = kok && (gn < N);
            long gnc = ok ? gn : 0;
            int nb = ok ? 16 : 0;
            cpasync16(sst + 2 * PLANE_B + soff, Bh + gnc * ldB + gkc, nb);
            cpasync16(sst + 3 * PLANE_B + soff, Bl + gnc * ldB + gkc, nb);
        }
    }
}

__global__ void __launch_bounds__(256)
gemm_bf16_kernel(const bf16* __restrict__ Ah, const bf16* __restrict__ Al,
                 const bf16* __restrict__ Bh, const bf16* __restrict__ Bl,
                 const float* __restrict__ bias, float* __restrict__ C,
                 int M, int N, int K, int act, const int* __restrict__ Mdev,
                 int ldA, int ldB)
{
    if (Mdev) {
        M = min(M, *Mdev);
        if ((long)blockIdx.y * 128 >= (long)M) return;
    }
    extern __shared__ __align__(16) bf16 dsm[];
    unsigned sbase = (unsigned)__cvta_generic_to_shared(dsm);

    int tid = threadIdx.x;
    int warp = tid >> 5, lane = tid & 31;
    int wm = (warp & 1) * 64;
    int wn = (warp >> 1) * 32;
    long row0 = (long)blockIdx.y * 128;
    long col0 = (long)blockIdx.x * 128;

    float acc[4][4][4];
#pragma unroll
    for (int a = 0; a < 4; a++)
#pragma unroll
        for (int b = 0; b < 4; b++)
#pragma unroll
            for (int c = 0; c < 4; c++) acc[a][b][c] = 0.f;

    int am_r = (lane & 7) + ((lane >> 3) & 1) * 8;
    int a_c8 = ((lane >> 4) & 1) * 8;
    int b_r  = (lane & 7) + ((lane >> 4) & 1) * 8;
    int b_c8 = ((lane >> 3) & 1) * 8;

    int T = (K + 31) / 32;

#pragma unroll
    for (int kt = 0; kt < GSTG; kt++) {
        gbf_prefetch(Ah, Al, Bh, Bl, row0, col0, M, N, K, ldA, ldB, kt, T, sbase, kt, tid);
        asm volatile("cp.async.commit_group;\n");
    }

    for (int kt = 0; kt < T; kt++) {
        asm volatile("cp.async.wait_group %0;\n" :: "n"(GSTG - 1));
        __syncthreads();

        int stg = kt % GSTG;
        unsigned sst = sbase + (unsigned)stg * STAGE_B;
        unsigned aB = sst;
        unsigned bB = sst + 2 * PLANE_B;

#pragma unroll
        for (int ks = 0; ks < 2; ks++) {
            int kb = ks * 16;
            unsigned bh[2][4], bl[2][4];
#pragma unroll
            for (int pp = 0; pp < 2; pp++) {
                unsigned addr = bB + (unsigned)(((wn + pp * 16 + b_r) * LDSB + kb + b_c8) * 2);
                LDSM4(bh[pp], addr);
                LDSM4(bl[pp], addr + PLANE_B);
            }
            unsigned ahf[4][4], alf[4][4];
#pragma unroll
            for (int mi = 0; mi < 4; mi++) {
                unsigned addr = aB + (unsigned)(((wm + mi * 16 + am_r) * LDSB + kb + a_c8) * 2);
                LDSM4(ahf[mi], addr);
                LDSM4(alf[mi], addr + PLANE_B);
            }
#pragma unroll
            for (int mi = 0; mi < 4; mi++)
#pragma unroll
                for (int ni = 0; ni < 4; ni++)
                    MMA_BF16(acc[mi][ni], ahf[mi], (&bh[ni >> 1][(ni & 1) * 2]));
#pragma unroll
            for (int mi = 0; mi < 4; mi++)
#pragma unroll
                for (int ni = 0; ni < 4; ni++)
                    MMA_BF16(acc[mi][ni], ahf[mi], (&bl[ni >> 1][(ni & 1) * 2]));
#pragma unroll
            for (int mi = 0; mi < 4; mi++)
#pragma unroll
                for (int ni = 0; ni < 4; ni++)
                    MMA_BF16(acc[mi][ni], alf[mi], (&bh[ni >> 1][(ni & 1) * 2]));
        }
        __syncthreads();
        gbf_prefetch(Ah, Al, Bh, Bl, row0, col0, M, N, K, ldA, ldB, kt + GSTG, T, sbase, stg, tid);
        asm volatile("cp.async.commit_group;\n");
    }

#pragma unroll
    for (int mi = 0; mi < 4; mi++) {
#pragma unroll
        for (int ni = 0; ni < 4; ni++) {
            long r = row0 + wm + mi * 16 + (lane >> 2);
            long c = col0 + wn + ni * 8 + (lane & 3) * 2;
#pragma unroll
            for (int half = 0; half < 2; half++) {
                long rr = r + half * 8;
                if (rr >= M) continue;
#pragma unroll
                for (int e = 0; e < 2; e++) {
                    long cc = c + e;
                    if (cc >= N) continue;
                    float v = acc[mi][ni][half * 2 + e];
                    if (bias) v += bias[cc];
                    if (act == 1) v = fmaxf(v, 0.f);
                    C[(size_t)rr * N + cc] = v;
                }
            }
        }
    }
}

static void gemm_bf16(const bf16* Ah, const bf16* Al, const bf16* Bh, const bf16* Bl,
                      const float* bias, float* C, int M, int N, int K, int act,
                      const int* Mdev = nullptr, int ldA = 0, int ldB = 0,
                      cudaStream_t st = 0)
{
    static int attr_done = 0;
    if (!attr_done) {
        cudaFuncSetAttribute(gemm_bf16_kernel,
                             cudaFuncAttributeMaxDynamicSharedMemorySize, GSTG * STAGE_B);
        attr_done = 1;
    }
    if (ldA == 0) ldA = K;
    if (ldB == 0) ldB = K;
    dim3 grid((N + 127) / 128, (M + 127) / 128);
    gemm_bf16_kernel<<<grid, 256, GSTG * STAGE_B, st>>>(Ah, Al, Bh, Bl, bias, C, M, N, K, act, Mdev, ldA, ldB);
}

// ================= conversion kernels =================
__device__ __forceinline__ void split1(float f, bf16& h, bf16& l)
{
    h = __float2bfloat16(f);
    l = __float2bfloat16(f - __bfloat162float(h));
}

__global__ void split_kernel(const float* __restrict__ x, bf16* __restrict__ hi,
                             bf16* __restrict__ lo, size_t n4)
{
    size_t i = (size_t)blockIdx.x * blockDim.x + threadIdx.x;
    if (i >= n4) return;
    float4 f = ((const float4*)x)[i];
    bf16 h0, l0, h1, l1, h2, l2, h3, l3;
    split1(f.x, h0, l0); split1(f.y, h1, l1); split1(f.z, h2, l2); split1(f.w, h3, l3);
    bf162 vh0; vh0.x = h0; vh0.y = h1;
    bf162 vh1; vh1.x = h2; vh1.y = h3;
    bf162 vl0; vl0.x = l0; vl0.y = l1;
    bf162 vl1; vl1.x = l2; vl1.y = l3;
    ((bf162*)hi)[i * 2] = vh0; ((bf162*)hi)[i * 2 + 1] = vh1;
    ((bf162*)lo)[i * 2] = vl0; ((bf162*)lo)[i * 2 + 1] = vl1;
}

static void split(const float* x, bf16* hi, bf16* lo, size_t n, cudaStream_t st = 0)
{
    size_t n4 = n / 4;
    split_kernel<<<(unsigned)((n4 + 255) / 256), 256, 0, st>>>(x, hi, lo, n4);
}

__global__ void transpose_split_kernel(const float* __restrict__ B, bf16* __restrict__ Th,
                                       bf16* __restrict__ Tl, int K, int N)
{
    __shared__ float tile[32][33];
    int k0 = blockIdx.y * 32, n0 = blockIdx.x * 32;
    int tx = threadIdx.x, ty = threadIdx.y;  // 32 x 8
#pragma unroll
    for (int i = 0; i < 32; i += 8) {
        int k = k0 + ty + i, n = n0 + tx;
        tile[ty + i][tx] = (k < K && n < N) ? B[(size_t)k * N + n] : 0.f;
    }
    __syncthreads();
#pragma unroll
    for (int i = 0; i < 32; i += 8) {
        int n = n0 + ty + i, k = k0 + tx;
        if (n < N && k < K) {
            float f = tile[tx][ty + i];
            bf16 h, l; split1(f, h, l);
            Th[(size_t)n * K + k] = h;
            Tl[(size_t)n * K + k] = l;
        }
    }
}

// ---------------- fast activations ----------------
__device__ __forceinline__ float fsig(float x)
{
    return __fdividef(1.f, 1.f + __expf(-x));
}
__device__ __forceinline__ float ftanh(float x)
{
    x = fminf(fmaxf(x, -15.f), 15.f);
    float e = __expf(-2.f * x);
    return __fdividef(1.f - e, 1.f + e);
}

// ---------------- length-compaction permutation ----------------
__global__ void build_perm_kernel(const int* __restrict__ lens)
{
    __shared__ int slens[Mlstm];
    __shared__ int bins[Lq + 1];
    __shared__ int offs[Lq + 1];
    int tid = threadIdx.x;
    if (tid <= Lq) bins[tid] = 0;
    __syncthreads();
    for (int i = tid; i < Mlstm; i += blockDim.x) {
        int l = lens[i];
        slens[i] = l;
        atomicAdd(&bins[l], 1);
    }
    __syncthreads();
    if (tid == 0) {
        int off = 0;
        for (int l = Lq; l >= 0; l--) { offs[l] = off; off += bins[l]; }
        int c = 0;
        for (int t = Lq - 1; t >= 0; t--) { c += bins[t + 1]; g_cnt[t] = c; }
        int cur[Lq + 1];
        for (int l = 0; l <= Lq; l++) cur[l] = offs[l];
        for (int i = 0; i < Mlstm; i++) {
            int l = slens[i];
            g_perm[cur[l]++] = i;
        }
        for (int i = 0; i < Mlstm; i++) g_iperm[g_perm[i]] = i;
    }
}

// ---------------- small custom kernels ----------------
__global__ void build_enc_kernel(const float* __restrict__ eo, const int* __restrict__ etype,
                                 const int* __restrict__ eid, const float* __restrict__ temb,
                                 const float* __restrict__ iemb, float* __restrict__ enc)
{
    int bs = blockIdx.x;
    const float* src = eo + (long)bs * HBq;
    float* dst = enc + (long)bs * D0q;
    int ty = etype[bs], idv = eid[bs];
    for (int j = threadIdx.x; j < D0q; j += blockDim.x) {
        float v;
        if (j < HBq)            v = src[j];
        else if (j < HBq + DTq) v = temb[ty * DTq + (j - HBq)];
        else                    v = iemb[idv * DIq + (j - HBq - DTq)];
        dst[j] = v;
    }
}

__global__ void softmax256_kernel(float* __restrict__ x)
{
    int row = blockIdx.x;
    int tid = threadIdx.x;
    float v = x[(long)row * 256 + tid];
    __shared__ float red[8];
    int lane = tid & 31, warp = tid >> 5;
    float m = v;
#pragma unroll
    for (int o = 16; o > 0; o >>= 1) m = fmaxf(m, __shfl_xor_sync(0xffffffffu, m, o));
    if (lane == 0) red[warp] = m;
    __syncthreads();
    if (tid == 0) {
        float mm = red[0];
        for (int w = 1; w < 8; w++) mm = fmaxf(mm, red[w]);
        red[0] = mm;
    }
    __syncthreads();
    float mx = red[0];
    float e = expf(v - mx);
    float s = e;
#pragma unroll
    for (int o = 16; o > 0; o >>= 1) s += __shfl_xor_sync(0xffffffffu, s, o);
    __shared__ float red2[8];
    if (lane == 0) red2[warp] = s;
    __syncthreads();
    if (tid == 0) {
        float ss = 0.f;
        for (int w = 0; w < 8; w++) ss += red2[w];
        red2[0] = ss;
    }
    __syncthreads();
    x[(long)row * 256 + tid] = e / red2[0];
}

__global__ void gather_ih_l0_kernel(const float* __restrict__ proj, const int* __restrict__ nodes,
                                    float* __restrict__ ih)
{
    int r = blockIdx.x;
    int t = 1 + r / Mlstm, i = r % Mlstm;
    if (i >= g_cnt[t]) return;
    int orig = g_perm[i];
    int b = orig / (Pq * Kq);
    int node = nodes[orig * Lq + t];
    const float4* src = (const float4*)(proj + ((size_t)(b * Nq + node)) * BANK4q);
    float4* dst = (float4*)(ih + ((size_t)t * Mlstm + i) * BANK4q);
    for (int j = threadIdx.x; j < BANK4q / 4; j += blockDim.x) dst[j] = src[j];
}

__global__ void gather_w64_kernel(const float* __restrict__ src, const int* __restrict__ nodes,
                                  float* __restrict__ dst, int cslot)
{
    int i = blockIdx.x;
    if (i >= g_cnt[cslot]) return;
    int orig = g_perm[i];
    int b = orig / (Pq * Kq);
    int node = nodes[orig * Lq];
    const float4* s = (const float4*)(src + ((size_t)(b * Nq + node)) * BANK4q);
    float4* d = (float4*)(dst + (size_t)i * BANK4q);
    for (int j = threadIdx.x; j < BANK4q / 4; j += blockDim.x) d[j] = s[j];
}

__global__ void cand_cell_kernel(const float* __restrict__ proj, float* __restrict__ ccand,
                                 bf16* __restrict__ hch, bf16* __restrict__ hcl)
{
    int i = blockIdx.y;
    int j = blockIdx.x * blockDim.x + threadIdx.x;
    if (j >= BANKq) return;
    const float* g = proj + (size_t)i * BANK4q;
    float gi = g[j], gg = g[2 * BANKq + j], go = g[3 * BANKq + j];
    float cn = fsig(gi) * ftanh(gg);
    float hn = fsig(go) * ftanh(cn);
    ccand[(size_t)i * BANKq + j] = cn;
    bf16 h, l; split1(hn, h, l);
    hch[(size_t)i * BANKq + j] = h;
    hcl[(size_t)i * BANKq + j] = l;
}

__global__ void gather0_kernel(const bf16* __restrict__ hch, const bf16* __restrict__ hcl,
                               const float* __restrict__ ccand, const int* __restrict__ nodes,
                               bf16* __restrict__ sh, bf16* __restrict__ sl,
                               float* __restrict__ c,
                               bf16* __restrict__ seq_hi, bf16* __restrict__ seq_lo,
                               float* __restrict__ hs)
{
    int i = blockIdx.x;
    int orig = g_perm[i];
    int b = orig / (Pq * Kq);
    size_t idx = ((size_t)(b * Nq + nodes[orig * Lq])) * BANKq;
    size_t dst = (size_t)i * BANKq;
    for (int j = threadIdx.x; j < BANKq; j += blockDim.x) {
        bf16 h = hch[idx + j], l = hcl[idx + j];
        sh[dst + j] = h;
        sl[dst + j] = l;
        c[dst + j] = ccand[idx + j];
        if (seq_hi) { seq_hi[dst + j] = h; seq_lo[dst + j] = l; }
        if (hs) hs[dst + j] = __bfloat162float(h) + __bfloat162float(l);
    }
}

__global__ void lstm_cell_kernel(const float* __restrict__ ih, const float* __restrict__ hh,
                                 bf16* __restrict__ h_hi, bf16* __restrict__ h_lo,
                                 bf16* __restrict__ seq_hi, bf16* __restrict__ seq_lo,
                                 float* __restrict__ c, float* __restrict__ hs, int t)
{
    int i = blockIdx.y;
    if (i >= g_cnt[t]) return;
    int j = blockIdx.x * blockDim.x + threadIdx.x;
    if (j >= BANKq) return;
    const float* g = ih + ((size_t)t * Mlstm + i) * BANK4q;
    const float* hr = hh + (size_t)i * BANK4q;
    float gi = g[j] + hr[j];
    float gf = g[BANKq + j] + hr[BANKq + j];
    float gg = g[2 * BANKq + j] + hr[2 * BANKq + j];
    float go = g[3 * BANKq + j] + hr[3 * BANKq + j];
    float cp = c[(size_t)i * BANKq + j];
    float cn = fsig(gf) * cp + fsig(gi) * ftanh(gg);
    float hn = fsig(go) * ftanh(cn);
    c[(size_t)i * BANKq + j] = cn;
    bf16 h, l; split1(hn, h, l);
    h_hi[(size_t)i * BANKq + j] = h;
    h_lo[(size_t)i * BANKq + j] = l;
    if (seq_hi) {
        seq_hi[((size_t)t * Mlstm + i) * BANKq + j] = h;
        seq_lo[((size_t)t * Mlstm + i) * BANKq + j] = l;
    }
    if (hs) hs[((size_t)t * Mlstm + i) * BANKq + j] = hn;
}

__global__ void maxpool_split_kernel(const float* __restrict__ hs, const int* __restrict__ lens,
                                     bf16* __restrict__ hi, bf16* __restrict__ lo)
{
    int i = blockIdx.y;
    int j = blockIdx.x * blockDim.x + threadIdx.x;
    if (j >= BANKq) return;
    int orig = g_perm[i];
    int len = lens[orig];
    float m = -1e9f;
    const float* base = hs + (size_t)i * BANKq + j;
    for (int t = 0; t < Lq; t++)
        if (t < len) m = fmaxf(m, base[(size_t)t * Mlstm * BANKq]);
    float r = (len > 0) ? m : 0.f;
    bf16 h, l; split1(r, h, l);
    hi[(size_t)i * BANKq + j] = h;
    lo[(size_t)i * BANKq + j] = l;
}

__global__ void zero_kv_tail_kernel(float* __restrict__ kb, float* __restrict__ vb)
{
    int i = blockIdx.x;
    if (i < g_cnt[0]) return;
    float4* k4 = (float4*)(kb + (size_t)i * BANKq);
    float4* v4 = (float4*)(vb + (size_t)i * BANKq);
    float4 z = {0.f, 0.f, 0.f, 0.f};
    for (int j = threadIdx.x; j < BANKq / 4; j += blockDim.x) { k4[j] = z; v4[j] = z; }
}

__global__ void gather_ht_kernel(const float* __restrict__ feats, const int* __restrict__ htp,
                                 float* __restrict__ hf, float* __restrict__ tf,
                                 bf16* __restrict__ qh, bf16* __restrict__ ql)
{
    int bp = blockIdx.x;
    int b = bp / Pq;
    int h0 = htp[bp * 2 + 0], t0 = htp[bp * 2 + 1];
    h0 = (h0 == 0) ? 0 : h0 - 1;
    t0 = (t0 == 0) ? 0 : t0 - 1;
    const float* hsrc = feats + ((size_t)b * Nq + (Nq - Eq) + h0) * BANKq;
    const float* tsrc = feats + ((size_t)b * Nq + (Nq - Eq) + t0) * BANKq;
    for (int j = threadIdx.x; j < BANKq; j += blockDim.x) {
        float hv = hsrc[j], tv = tsrc[j];
        hf[(size_t)bp * BANKq + j] = hv;
        tf[(size_t)bp * BANKq + j] = tv;
        bf16 h, l; split1(hv - tv, h, l);
        qh[(size_t)bp * BANKq + j] = h;
        ql[(size_t)bp * BANKq + j] = l;
    }
}

__global__ void mha_attn_kernel(const float* __restrict__ q, const float* __restrict__ k,
                                const float* __restrict__ v, const int* __restrict__ plens,
                                const float* __restrict__ rmask,
                                bf16* __restrict__ ctx_hi, bf16* __restrict__ ctx_lo,
                                int* __restrict__ validany)
{
    int bp = blockIdx.x;
    int tid = threadIdx.x;
    int warp = tid >> 5, lane = tid & 31;
    __shared__ float sc[NHq][Kq];
    __shared__ float aw[NHq][Kq];
    __shared__ int vm[Kq];
    __shared__ int slot[Kq];
    if (tid < Kq) {
        vm[tid] = (rmask[bp] > 0.f && plens[bp * Kq + tid] > 0) ? 1 : 0;
        slot[tid] = g_iperm[bp * Kq + tid];
    }
    __syncthreads();
    {
        int h = warp / Kq, kk = warp % Kq;
        const float* qh = q + (size_t)bp * BANKq + h * DHq;
        const float* kh = k + (size_t)slot[kk] * BANKq + h * DHq;
        float s = 0.f;
        for (int d = lane; d < DHq; d += 32) s += qh[d] * kh[d];
#pragma unroll
        for (int o = 16; o > 0; o >>= 1) s += __shfl_xor_sync(0xffffffffu, s, o);
        if (lane == 0) {
            s = s / sqrtf((float)DHq);
            sc[h][kk] = vm[kk] ? s : -1e9f;
        }
    }
    __syncthreads();
    if (tid < NHq) {
        int h = tid;
        float m = fmaxf(fmaxf(sc[h][0], sc[h][1]), sc[h][2]);
        float e0 = expf(sc[h][0] - m), e1 = expf(sc[h][1] - m), e2 = expf(sc[h][2] - m);
        float s = e0 + e1 + e2;
        aw[h][0] = e0 / s; aw[h][1] = e1 / s; aw[h][2] = e2 / s;
    }
    if (tid == 0) validany[bp] = (vm[0] | vm[1] | vm[2]);
    __syncthreads();
    const float* v0 = v + (size_t)slot[0] * BANKq;
    const float* v1 = v + (size_t)slot[1] * BANKq;
    const float* v2 = v + (size_t)slot[2] * BANKq;
    for (int j = tid; j < BANKq; j += blockDim.x) {
        int h = j / DHq;
        float r = aw[h][0] * v0[j] + aw[h][1] * v1[j] + aw[h][2] * v2[j];
        bf16 hh2, ll2; split1(r, hh2, ll2);
        ctx_hi[(size_t)bp * BANKq + j] = hh2;
        ctx_lo[(size_t)bp * BANKq + j] = ll2;
    }
}

// bank rows -> split bf16 (168 rows)
__global__ void bank_split_kernel(const float* __restrict__ feats,
                                  bf16* __restrict__ bh, bf16* __restrict__ bl)
{
    int i = blockIdx.x;
    int b = i / Eq, e = i % Eq;
    const float* src = feats + ((size_t)b * Nq + (Nq - Eq) + e) * BANKq;
    size_t dst = (size_t)i * BANKq;
    for (int j = threadIdx.x; j < BANKq; j += blockDim.x) {
        bf16 h, l; split1(src[j], h, l);
        bh[dst + j] = h;
        bl[dst + j] = l;
    }
}

// of_ap = [abs, prod] (1024 x 3152) split bf16 -- depends only on hf/tf (side stream)
__global__ void build_of_ap_kernel(const float* __restrict__ hf, const float* __restrict__ tf,
                                   bf16* __restrict__ oh, bf16* __restrict__ ol)
{
    int bp = blockIdx.x;
    const float* hr = hf + (size_t)bp * BANKq;
    const float* tr = tf + (size_t)bp * BANKq;
    size_t base = (size_t)bp * BANK2q;
    for (int j = threadIdx.x; j < BANK2q; j += blockDim.x) {
        int seg = j / BANKq, jj = j - seg * BANKq;
        float v = (seg == 0) ? fabsf(hr[jj] - tr[jj]) : hr[jj] * tr[jj];
        bf16 h, l; split1(v, h, l);
        oh[base + j] = h;
        ol[base + j] = l;
    }
}

// of_pi = masked pinfo (1024 x 1576) split bf16 (main tail)
__global__ void build_of_pi_kernel(const float* __restrict__ pinfo, const int* __restrict__ validany,
                                   bf16* __restrict__ oh, bf16* __restrict__ ol)
{
    int bp = blockIdx.x;
    int va = validany[bp];
    const float* pr = pinfo + (size_t)bp * BANKq;
    size_t base = (size_t)bp * BANKq;
    for (int j = threadIdx.x; j < BANKq; j += blockDim.x) {
        float v = va ? pr[j] : 0.f;
        bf16 h, l; split1(v, h, l);
        oh[base + j] = h;
        ol[base + j] = l;
    }
}

// hid[r] = relu(hid[r] + p1[bank(h_r)] + p2[bank(t_r)] + p3[r])
__global__ void combine_pred_kernel(float* __restrict__ hid, const float* __restrict__ p1,
                                    const float* __restrict__ p2, const float* __restrict__ p3,
                                    const int* __restrict__ htp)
{
    int r = blockIdx.x;
    int b = r / Pq;
    int h0 = htp[r * 2 + 0], t0 = htp[r * 2 + 1];
    h0 = (h0 == 0) ? 0 : h0 - 1;
    t0 = (t0 == 0) ? 0 : t0 - 1;
    const float* q1 = p1 + (size_t)(b * Eq + h0) * BANK5q;
    const float* q2 = p2 + (size_t)(b * Eq + t0) * BANK5q;
    const float* q3 = p3 + (size_t)r * BANK5q;
    float* hr = hid + (size_t)r * BANK5q;
    for (int j = threadIdx.x; j < BANK5q; j += blockDim.x)
        hr[j] = fmaxf(hr[j] + q1[j] + q2[j] + q3[j], 0.f);
}

// small head for the N=2 output
__global__ void __launch_bounds__(256)
head2_kernel(const float* __restrict__ hid, const float* __restrict__ bW,
             const float* __restrict__ bb, float* __restrict__ out2)
{
    int m = blockIdx.x;
    int tid = threadIdx.x, lane = tid & 31, warp = tid >> 5;
    const float* hr = hid + (size_t)m * BANK5q;
    float a0 = 0.f, a1 = 0.f;
    for (int k = tid; k < BANK5q; k += 256) {
        float h = hr[k];
        a0 = fmaf(h, bW[(size_t)k * 2], a0);
        a1 = fmaf(h, bW[(size_t)k * 2 + 1], a1);
    }
#pragma unroll
    for (int o = 16; o > 0; o >>= 1) {
        a0 += __shfl_xor_sync(0xffffffffu, a0, o);
        a1 += __shfl_xor_sync(0xffffffffu, a1, o);
    }
    __shared__ float r0[8], r1[8];
    if (lane == 0) { r0[warp] = a0; r1[warp] = a1; }
    __syncthreads();
    if (tid == 0) {
        float s0 = 0.f, s1 = 0.f;
        for (int w = 0; w < 8; w++) { s0 += r0[w]; s1 += r1[w]; }
        out2[(size_t)m * 2 + 0] = s0 + bb[0];
        out2[(size_t)m * 2 + 1] = s1 + bb[1];
    }
}

// ---------------- orchestration ----------------
extern "C" void kernel_launch(void* const* d_in, const int* in_sizes, int n_in,
                              void* d_out, int out_size)
{
    const float* encoder_outputs = (const float*)d_in[0];
    const int*   entity_type     = (const int*)  d_in[1];
    const int*   entity_id       = (const int*)  d_in[2];
    const float* sub2words       = (const float*)d_in[3];
    const float* adj             = (const float*)d_in[4];
    const int*   h_t_pairs       = (const int*)  d_in[5];
    const float* rel_mask        = (const float*)d_in[6];
    const int*   path_nodes      = (const int*)  d_in[7];
    const int*   path_lens       = (const int*)  d_in[8];
    const float* type_emb        = (const float*)d_in[9];
    const float* id_emb          = (const float*)d_in[10];
    const float* gcn0_W          = (const float*)d_in[11];
    const float* gcn0_b          = (const float*)d_in[12];
    const float* gcn_W           = (const float*)d_in[13];
    const float* gcn_b           = (const float*)d_in[14];
    const float* attn_Wq         = (const float*)d_in[15];
    const float* attn_Wk         = (const float*)d_in[16];
    const float* attn_Wv         = (const float*)d_in[17];
    const float* lstm_Wih        = (const float*)d_in[18];
    const float* lstm_Whh        = (const float*)d_in[19];
    const float* lstm_b          = (const float*)d_in[20];
    const float* mha_inW         = (const float*)d_in[21];
    const float* mha_inb         = (const float*)d_in[22];
    const float* mha_outW        = (const float*)d_in[23];
    const float* mha_outb        = (const float*)d_in[24];
    const float* pred_W          = (const float*)d_in[25];
    const float* pred_b          = (const float*)d_in[26];
    const float* mW              = (const float*)d_in[27];
    const float* mb              = (const float*)d_in[28];
    const float* bW              = (const float*)d_in[29];
    const float* bb              = (const float*)d_in[30];
    float* out = (float*)d_out;

    void* p;
#define SYMF(var, sym) cudaGetSymbolAddress(&p, sym); float* var = (float*)p;
#define SYMB(var, sym) cudaGetSymbolAddress(&p, sym); bf16* var = (bf16*)p;
    SYMF(enc,   g_enc);    SYMF(feats, g_feats);  SYMF(tmp,   g_tmp);
    SYMF(x1,    g_x1);     SYMF(xq,    g_xq);     SYMF(xk,    g_xk);
    SYMF(xv,    g_xv);     SYMF(att,   g_att);
    SYMF(ih,    g_ih);     SYMF(hh,    g_hh);
    SYMF(cbuf,  g_c);      SYMF(hs1,   g_hs1);
    SYMF(hf,    g_hf);     SYMF(tf,    g_tf);
    SYMF(qb,    g_q);      SYMF(ccand, g_ccand);
    SYMF(kb,    g_k);      SYMF(vb,    g_v);
    SYMF(pinfo, g_pinfo);  SYMF(pp,    g_pp);     SYMF(p3,    g_p3);
    SYMF(hid,   g_hid);
    SYMB(ah,  g_ah);  SYMB(al,  g_al);
    SYMB(sh,  g_sh);  SYMB(sl,  g_sl);
    SYMB(hch, g_hch); SYMB(hcl, g_hcl);
    SYMB(q2h, g_q2h); SYMB(q2l, g_q2l);
    SYMB(bkh, g_bkh); SYMB(bkl, g_bkl);
    SYMB(oph, g_oph); SYMB(opl, g_opl);
    SYMB(w1h, g_w1h); SYMB(w1l, g_w1l);
    SYMB(w2h, g_w2h); SYMB(w2l, g_w2l);
    SYMB(w3h, g_w3h); SYMB(w3l, g_w3l);
    SYMB(w4h, g_w4h); SYMB(w4l, g_w4l);
    SYMB(mwh, g_mwh); SYMB(mwl, g_mwl);
    SYMB(owh, g_owh); SYMB(owl, g_owl);
    SYMB(wph, g_wph); SYMB(wpl, g_wpl);
    cudaGetSymbolAddress(&p, g_validany); int* validany = (int*)p;
    cudaGetSymbolAddress(&p, g_cnt);      int* cntdev = (int*)p;
#undef SYMF
#undef SYMB

    // ---- persistent side stream + events ----
    static cudaStream_t s2 = nullptr;
    static cudaEvent_t evFork = nullptr, evW0 = nullptr, evW1 = nullptr, evW2 = nullptr,
                       evFeats = nullptr, evQ = nullptr, evSide = nullptr;
    if (!s2) {
        cudaStreamCreateWithFlags(&s2, cudaStreamNonBlocking);
        cudaEventCreateWithFlags(&evFork,  cudaEventDisableTiming);
        cudaEventCreateWithFlags(&evW0,    cudaEventDisableTiming);
        cudaEventCreateWithFlags(&evW1,    cudaEventDisableTiming);
        cudaEventCreateWithFlags(&evW2,    cudaEventDisableTiming);
        cudaEventCreateWithFlags(&evFeats, cudaEventDisableTiming);
        cudaEventCreateWithFlags(&evQ,     cudaEventDisableTiming);
        cudaEventCreateWithFlags(&evSide,  cudaEventDisableTiming);
    }

    const size_t W4 = (size_t)BANK4q * BANKq;

    // ======== FORK: side stream does all weight prep ========
    cudaEventRecord(evFork, 0);
    cudaStreamWaitEvent(s2, evFork, 0);

    split(lstm_Wih,      w1h, w1l, W4, s2);
    split(lstm_Whh,      w2h, w2l, W4, s2);
    cudaEventRecord(evW0, s2);
    split(lstm_Wih + W4, w3h, w3l, W4, s2);
    split(lstm_Whh + W4, w4h, w4l, W4, s2);
    cudaEventRecord(evW1, s2);
    split(mha_inW,  mwh, mwl, (size_t)3 * BANKq * BANKq, s2);
    split(mha_outW, owh, owl, (size_t)BANKq * BANKq, s2);
    {
        dim3 grid((BANK5q + 31) / 32, (BANK5q + 31) / 32);
        transpose_split_kernel<<<grid, dim3(32, 8), 0, s2>>>(pred_W, wph, wpl, BANK5q, BANK5q);
    }
    cudaEventRecord(evW2, s2);

    // ======== main stream: perm + enc + GCN ========
    build_perm_kernel<<<1, 1024>>>(path_lens);
    build_enc_kernel<<<Bq * Sq, 256>>>(encoder_outputs, entity_type, entity_id, type_emb, id_emb, enc);

    gemm(false, sub2words, enc, nullptr, nullptr, feats,
         Nq, D0q, Sq, Sq, D0q, BANKq, 0,
         (long)Nq * Sq, (long)Sq * D0q, (long)Nq * BANKq, 0, Bq, 1.f, 0);
    gemm(false, adj, feats, nullptr, nullptr, tmp,
         Nq, D0q, Nq, Nq, BANKq, D0q, 0,
         (long)Nq * Nq, (long)Nq * BANKq, (long)Nq * D0q, 0, Bq, 1.f, 0);
    gemm(false, tmp, gcn0_W, gcn0_b, nullptr, feats + 808,
         Nq, Gq, D0q, D0q, Gq, BANKq, 0,
         (long)Nq * D0q, 0, (long)Nq * BANKq, 0, Bq, 1.f, 0);

    int xoff[NLq]   = {808, 1064};
    int outoff[NLq] = {1064, 1320};
    for (int l = 0; l < NLq; l++) {
        const float* x = feats + xoff[l];
        gemm(false, adj, x, nullptr, nullptr, tmp,
             Nq, Gq, Nq, Nq, BANKq, Gq, 0,
             (long)Nq * Nq, (long)Nq * BANKq, (long)Nq * Gq, 0, Bq, 1.f, 0);
        gemm(false, tmp, gcn_W + (long)l * Gq * Gq, gcn_b + l * Gq, nullptr, x1,
             Nq, Gq, Gq, Gq, Gq, Gq, 0,
             (long)Nq * Gq, 0, (long)Nq * Gq, 0, Bq, 1.f, 1);
        gemm(false, x, attn_Wq + (long)l * Gq * Gq, nullptr, nullptr, xq,
             Nq, Gq, Gq, BANKq, Gq, Gq, 0,
             (long)Nq * BANKq, 0, (long)Nq * Gq, 0, Bq, 1.f, 0);
        gemm(false, x1, attn_Wk + (long)l * Gq * Gq, nullptr, nullptr, xk,
             Nq, Gq, Gq, Gq, Gq, Gq, 0,
             (long)Nq * Gq, 0, (long)Nq * Gq, 0, Bq, 1.f, 0);
        gemm(false, x1, attn_Wv + (long)l * Gq * Gq, nullptr, nullptr, xv,
             Nq, Gq, Gq, Gq, Gq, Gq, 0,
             (long)Nq * Gq, 0, (long)Nq * Gq, 0, Bq, 1.f, 0);
        gemm(true, xq, xk, nullptr, nullptr, att,
             Nq, Nq, Gq, Gq, Gq, Nq, 0,
             (long)Nq * Gq, (long)Nq * Gq, (long)Nq * Nq, 0, Bq, 0.0625f, 0);
        softmax256_kernel<<<Bq * Nq, 256>>>(att);
        gemm(false, att, xv, nullptr, x1, feats + outoff[l],
             Nq, Gq, Nq, Nq, Gq, BANKq, Gq,
             (long)Nq * Nq, (long)Nq * Gq, (long)Nq * BANKq, (long)Nq * Gq, Bq, 1.f, 1);
    }
    cudaEventRecord(evFeats, 0);

    // ======== side stream (after feats): q-branch + pred partials ========
    cudaStreamWaitEvent(s2, evFeats, 0);
    gather_ht_kernel<<<BPq, 256, 0, s2>>>(feats, h_t_pairs, hf, tf, q2h, q2l);
    gemm_bf16(q2h, q2l, mwh, mwl, mha_inb, qb, BPq, BANKq, BANKq, 0, nullptr, 0, 0, s2);
    cudaEventRecord(evQ, s2);
    bank_split_kernel<<<NBANKROWS, 256, 0, s2>>>(feats, bkh, bkl);
    float* p1 = pp;
    float* p2 = pp + (size_t)NBANKROWS * BANK5q;
    gemm_bf16(bkh, bkl, wph, wpl, nullptr, p1,
              NBANKROWS, BANK5q, BANKq, 0, nullptr, BANKq, BANK5q, s2);
    gemm_bf16(bkh, bkl, wph + BANKq, wpl + BANKq, nullptr, p2,
              NBANKROWS, BANK5q, BANKq, 0, nullptr, BANKq, BANK5q, s2);
    // abs/prod pred slab (76G MACs) runs here, overlapped with the LSTM
    build_of_ap_kernel<<<BPq, 256, 0, s2>>>(hf, tf, oph, opl);
    gemm_bf16(oph, opl, wph + 2 * BANKq, wpl + 2 * BANKq, nullptr, p3,
              BPq, BANK5q, BANK2q, 0, nullptr, BANK2q, BANK5q, s2);
    cudaEventRecord(evSide, s2);

    // ======== main stream: LSTM ========
    dim3 cg((BANKq + 255) / 256, Mlstm);
    dim3 cg1((BANKq + 255) / 256, BPq);

    cudaStreamWaitEvent(0, evW0, 0);
    // ----- layer 0 (prefix dedup + length compaction) -----
    {
        const float* b0 = lstm_b;
        split(feats, sh, sl, (size_t)Bq * Nq * BANKq);
        gemm_bf16(sh, sl, w1h, w1l, b0, hh, BPq, BANK4q, BANKq, 0);
        gather_ih_l0_kernel<<<3 * Mlstm, 256>>>(hh, path_nodes, ih);
        cand_cell_kernel<<<cg1, 256>>>(hh, ccand, hch, hcl);
        gather0_kernel<<<Mlstm, 256>>>(hch, hcl, ccand, path_nodes, sh, sl, cbuf, ah, al, nullptr);
        gemm_bf16(hch, hcl, w2h, w2l, nullptr, hid, BPq, BANK4q, BANKq, 0);
        gather_w64_kernel<<<Mlstm, 256>>>(hid, path_nodes, hh, 1);
        for (int t = 1; t < Lq; t++) {
            if (t > 1)
                gemm_bf16(sh, sl, w2h, w2l, nullptr, hh, Mlstm, BANK4q, BANKq, 0, cntdev + t);
            lstm_cell_kernel<<<cg, 256>>>(ih, hh, sh, sl, ah, al, cbuf, nullptr, t);
        }
    }

    cudaStreamWaitEvent(0, evW1, 0);
    // ----- layer 1 (same dedup + compaction) -----
    {
        const float* b1 = lstm_b + BANK4q;
        gemm_bf16(hch, hcl, w3h, w3l, b1, hid, BPq, BANK4q, BANKq, 0);
        for (int t = 1; t < Lq; t++)
            gemm_bf16(ah + (size_t)t * Mlstm * BANKq, al + (size_t)t * Mlstm * BANKq,
                      w3h, w3l, b1, ih + (size_t)t * Mlstm * BANK4q,
                      Mlstm, BANK4q, BANKq, 0, cntdev + t);
        cand_cell_kernel<<<cg1, 256>>>(hid, ccand, hch, hcl);
        gather0_kernel<<<Mlstm, 256>>>(hch, hcl, ccand, path_nodes, sh, sl, cbuf,
                                       nullptr, nullptr, hs1);
        gemm_bf16(hch, hcl, w4h, w4l, nullptr, hid, BPq, BANK4q, BANKq, 0);
        gather_w64_kernel<<<Mlstm, 256>>>(hid, path_nodes, hh, 1);
        for (int t = 1; t < Lq; t++) {
            if (t > 1)
                gemm_bf16(sh, sl, w4h, w4l, nullptr, hh, Mlstm, BANK4q, BANKq, 0, cntdev + t);
            lstm_cell_kernel<<<cg, 256>>>(ih, hh, sh, sl, nullptr, nullptr, cbuf, hs1, t);
        }
    }

    // 8) masked max-pool -> pe in COMPACTED order (split bf16 into ah/al)
    maxpool_split_kernel<<<cg, 256>>>(hs1, path_lens, ah, al);

    // 10-11) k/v projections (need mha weights only)
    cudaStreamWaitEvent(0, evW2, 0);
    gemm_bf16(ah, al, mwh + (size_t)BANKq * BANKq, mwl + (size_t)BANKq * BANKq,
              mha_inb + BANKq, kb, Mlstm, BANKq, BANKq, 0, cntdev + 0);
    gemm_bf16(ah, al, mwh + 2 * (size_t)BANKq * BANKq, mwl + 2 * (size_t)BANKq * BANKq,
              mha_inb + 2 * BANKq, vb, Mlstm, BANKq, BANKq, 0, cntdev + 0);
    zero_kv_tail_kernel<<<Mlstm, 256>>>(kb, vb);

    // 12) tiny attention over K=3 paths (needs qb from side)
    cudaStreamWaitEvent(0, evQ, 0);
    mha_attn_kernel<<<BPq, 384>>>(qb, kb, vb, path_lens, rel_mask, sh, sl, validany);

    // 13) pinfo
    gemm_bf16(sh, sl, owh, owl, mha_outb, pinfo, BPq, BANKq, BANKq, 0);

    // 14-15) pred: only the pinfo segment remains on the critical path
    build_of_pi_kernel<<<BPq, 256>>>(pinfo, validany, sh, sl);
    gemm_bf16(sh, sl, wph + 4 * (size_t)BANKq, wpl + 4 * (size_t)BANKq, pred_b, hid,
              BPq, BANK5q, BANKq, 0, nullptr, BANKq, BANK5q);
    cudaStreamWaitEvent(0, evSide, 0);
    combine_pred_kernel<<<BPq, 256>>>(hid, p1, p2, p3, h_t_pairs);

    // 16) output heads
    gemm(false, hid, mW, mb, nullptr, out,
         BPq, Rq, BANK5q, BANK5q, Rq, Rq, 0, 0, 0, 0, 0, 1, 1.f, 0);
    head2_kernel<<<BPq, 256>>>(hid, bW, bb, out + (size_t)BPq * Rq);
}

// round 17
// speedup vs baseline: 1.4567x; 1.4567x over previous
#include <cuda_runtime.h>
#include <cuda_bf16.h>
#include <math.h>
#include <stdio.h>

// ---------------- problem constants ----------------
#define Bq   4
#define Sq   512
#define Nq   256
#define Eq   42
#define Pq   256
#define Kq   3
#define Lq   4
#define HBq  768
#define DTq  20
#define DIq  20
#define Gq   256
#define NLq  2
#define Rq   97
#define NHq  4
#define D0q  808          // HB+DT+DI
#define BANKq 1576        // D0 + G*(NL+1)
#define BANK3q 4728       // 3*BANK (abs|prod|pinfo)
#define BANK4q 6304       // 4*BANK
#define BANK5q 7880       // 5*BANK
#define DHq  394          // BANK/NH
#define Mlstm (Bq*Pq*Kq)        // 3072
#define MlstmT (Mlstm*Lq)       // 12288
#define BPq  (Bq*Pq)            // 1024
#define NBANKROWS (Bq*Eq)       // 168 distinct entity-bank rows

typedef __nv_bfloat16 bf16;
typedef __nv_bfloat162 bf162;

// ---------------- scratch (static device memory; no allocations allowed) ----------------
__device__ float g_enc   [Bq*Sq*D0q];
__device__ float g_feats [Bq*Nq*BANKq];
__device__ float g_tmp   [Bq*Nq*D0q];
__device__ float g_x1    [Bq*Nq*Gq];
__device__ float g_xq    [Bq*Nq*Gq];
__device__ float g_xk    [Bq*Nq*Gq];
__device__ float g_xv    [Bq*Nq*Gq];
__device__ float g_att   [Bq*Nq*Nq];
__device__ float g_ih    [(size_t)MlstmT*BANK4q];   // t-major
__device__ float g_hh    [(size_t)Mlstm*BANK4q];
__device__ float g_c     [Mlstm*BANKq];
__device__ float g_hs1   [MlstmT*BANKq];            // t-major, compacted rows
__device__ float g_hf    [BPq*BANKq];
__device__ float g_tf    [BPq*BANKq];
__device__ float g_q     [BPq*BANKq];               // qb (side stream)
__device__ float g_ccand [BPq*BANKq];               // candidate c scratch
__device__ float g_k     [Mlstm*BANKq];
__device__ float g_v     [Mlstm*BANKq];
__device__ float g_pinfo [BPq*BANKq];
__device__ float g_pp    [2*(size_t)NBANKROWS*BANK5q]; // pred partials p1/p2
__device__ int   g_validany[BPq];
__device__ float g_hid   [BPq*BANK5q];              // also proj scratch

// length-compaction state
__device__ int g_perm[Mlstm];
__device__ int g_iperm[Mlstm];
__device__ int g_cnt[4];

// bf16 split scratch
__device__ bf16 g_ah  [(size_t)MlstmT*BANKq];       // layer-0 seq; later pe; later of_rest
__device__ bf16 g_al  [(size_t)MlstmT*BANKq];
__device__ bf16 g_sh  [(size_t)Mlstm*BANKq];
__device__ bf16 g_sl  [(size_t)Mlstm*BANKq];
__device__ bf16 g_hch [(size_t)BPq*BANKq];          // candidate h
__device__ bf16 g_hcl [(size_t)BPq*BANKq];
__device__ bf16 g_q2h [(size_t)BPq*BANKq];          // query split (side stream)
__device__ bf16 g_q2l [(size_t)BPq*BANKq];
__device__ bf16 g_bkh [(size_t)NBANKROWS*BANKq];    // bank split (side stream)
__device__ bf16 g_bkl [(size_t)NBANKROWS*BANKq];
__device__ bf16 g_w1h [(size_t)BANK4q*BANKq];       // Wih0
__device__ bf16 g_w1l [(size_t)BANK4q*BANKq];
__device__ bf16 g_w2h [(size_t)BANK4q*BANKq];       // Whh0
__device__ bf16 g_w2l [(size_t)BANK4q*BANKq];
__device__ bf16 g_w3h [(size_t)BANK4q*BANKq];       // Wih1
__device__ bf16 g_w3l [(size_t)BANK4q*BANKq];
__device__ bf16 g_w4h [(size_t)BANK4q*BANKq];       // Whh1
__device__ bf16 g_w4l [(size_t)BANK4q*BANKq];
__device__ bf16 g_mwh [3*(size_t)BANKq*BANKq];      // mha_inW
__device__ bf16 g_mwl [3*(size_t)BANKq*BANKq];
__device__ bf16 g_owh [(size_t)BANKq*BANKq];        // mha_outW
__device__ bf16 g_owl [(size_t)BANKq*BANKq];
__device__ bf16 g_wph [(size_t)BANK5q*BANK5q];
__device__ bf16 g_wpl [(size_t)BANK5q*BANK5q];

// ================= fp32 tiled GEMM (small GCN ops + head) =================
template <bool TRANSB>
__global__ void __launch_bounds__(256)
gemm32_kernel(const float* __restrict__ A, const float* __restrict__ B,
              const float* __restrict__ bias, const float* __restrict__ resid,
              float* __restrict__ C,
              int M, int N, int K,
              int lda, int ldb, int ldc, int ldr,
              long sA, long sB, long sC, long sR,
              float alpha, int act)
{
    int bz = blockIdx.z;
    A += bz * sA; B += bz * sB; C += bz * sC;
    if (resid) resid += bz * sR;

    int row0 = blockIdx.y * 32;
    int col0 = blockIdx.x * 32;

    __shared__ float As[32][33];
    __shared__ float Bs[32][33];

    int tid = threadIdx.x;
    int tx = tid & 15, ty = tid >> 4;

    float acc[2][2] = {{0.f, 0.f}, {0.f, 0.f}};

    for (int k0 = 0; k0 < K; k0 += 32) {
#pragma unroll
        for (int l = 0; l < 4; l++) {
            int idx = tid + l * 256;
            int m = idx >> 5, kk = idx & 31;
            int gr = row0 + m, gk = k0 + kk;
            As[kk][m] = (gr < M && gk < K) ? A[(long)gr * lda + gk] : 0.f;
        }
#pragma unroll
        for (int l = 0; l < 4; l++) {
            int idx = tid + l * 256;
            if (TRANSB) {
                int n = idx >> 5, kk = idx & 31;
                int gn = col0 + n, gk = k0 + kk;
                Bs[kk][n] = (gn < N && gk < K) ? B[(long)gn * ldb + gk] : 0.f;
            } else {
                int kk = idx >> 5, n = idx & 31;
                int gn = col0 + n, gk = k0 + kk;
                Bs[kk][n] = (gn < N && gk < K) ? B[(long)gk * ldb + gn] : 0.f;
            }
        }
        __syncthreads();
#pragma unroll
        for (int kk = 0; kk < 32; kk++) {
            float a0 = As[kk][ty], a1 = As[kk][ty + 16];
            float b0 = Bs[kk][tx], b1 = Bs[kk][tx + 16];
            acc[0][0] = fmaf(a0, b0, acc[0][0]);
            acc[0][1] = fmaf(a0, b1, acc[0][1]);
            acc[1][0] = fmaf(a1, b0, acc[1][0]);
            acc[1][1] = fmaf(a1, b1, acc[1][1]);
        }
        __syncthreads();
    }

#pragma unroll
    for (int i = 0; i < 2; i++) {
        int r = row0 + ty + 16 * i;
        if (r >= M) continue;
#pragma unroll
        for (int j = 0; j < 2; j++) {
            int cc = col0 + tx + 16 * j;
            if (cc >= N) continue;
            float v = acc[i][j] * alpha;
            if (bias) v += bias[cc];
            if (act == 1) v = fmaxf(v, 0.f);
            if (resid) v += resid[(long)r * ldr + cc];
            C[(long)r * ldc + cc] = v;
        }
    }
}

static void gemm(bool transB,
                 const float* A, const float* B, const float* bias, const float* resid, float* C,
                 int M, int N, int K, int lda, int ldb, int ldc, int ldr,
                 long sA, long sB, long sC, long sR, int batch, float alpha, int act,
                 cudaStream_t st = 0)
{
    dim3 grid((N + 31) / 32, (M + 31) / 32, batch);
    if (transB)
        gemm32_kernel<true><<<grid, 256, 0, st>>>(A, B, bias, resid, C, M, N, K, lda, ldb, ldc, ldr, sA, sB, sC, sR, alpha, act);
    else
        gemm32_kernel<false><<<grid, 256, 0, st>>>(A, B, bias, resid, C, M, N, K, lda, ldb, ldc, ldr, sA, sB, sC, sR, alpha, act);
}

// ================= bf16 split-precision tensor-core GEMM (R6 loop + Mdev + ld) =================
#define LDSB 40
#define GSTG 3
#define PLANE_E (128*LDSB)
#define PLANE_B (PLANE_E*2)
#define STAGE_B (4*PLANE_B)

#define MMA_BF16(d, a, b) asm volatile( \
    "mma.sync.aligned.m16n8k16.row.col.f32.bf16.bf16.f32 " \
    "{%0,%1,%2,%3}, {%4,%5,%6,%7}, {%8,%9}, {%0,%1,%2,%3};" \
    : "+f"((d)[0]), "+f"((d)[1]), "+f"((d)[2]), "+f"((d)[3]) \
    : "r"((a)[0]), "r"((a)[1]), "r"((a)[2]), "r"((a)[3]), "r"((b)[0]), "r"((b)[1]))

#define LDSM4(r, addr) asm volatile( \
    "ldmatrix.sync.aligned.m8n8.x4.shared.b16 {%0,%1,%2,%3}, [%4];" \
    : "=r"((r)[0]), "=r"((r)[1]), "=r"((r)[2]), "=r"((r)[3]) : "r"(addr))

__device__ __forceinline__ void cpasync16(unsigned saddr, const void* g, int srcbytes)
{
    asm volatile("cp.async.cg.shared.global [%0], [%1], 16, %2;\n"
                 :: "r"(saddr), "l"(g), "r"(srcbytes));
}

__device__ __forceinline__ void gbf_prefetch(
    const bf16* __restrict__ Ah, const bf16* __restrict__ Al,
    const bf16* __restrict__ Bh, const bf16* __restrict__ Bl,
    long row0, long col0, int M, int N, int K, int ldA, int ldB,
    int kt, int T, unsigned sbase, int stg, int tid)
{
    if (kt >= T) return;
    long k0 = (long)kt * 32;
    unsigned sst = sbase + (unsigned)stg * STAGE_B;
#pragma unroll
    for (int i = 0; i < 2; i++) {
        int c = tid + i * 256;
        int r = c >> 2;
        int ko = (c & 3) * 8;
        long gk = k0 + ko;
        bool kok = gk < K;
        long gkc = kok ? gk : 0;
        unsigned soff = (unsigned)((r * LDSB + ko) * 2);
        {
            long gr = row0 + r;
            bool ok = kok && (gr < M);
            long grc = ok ? gr : 0;
            int nb = ok ? 16 : 0;
            cpasync16(sst + soff,            Ah + grc * ldA + gkc, nb);
            cpasync16(sst + PLANE_B + soff,  Al + grc * ldA + gkc, nb);
        }
        {
            long gn = col0 + r;
            bool ok = kok && (gn < N);
            long gnc = ok ? gn : 0;
            int nb = ok ? 16 : 0;
            cpasync16(sst + 2 * PLANE_B + soff, Bh + gnc * ldB + gkc, nb);
            cpasync16(sst + 3 * PLANE_B + soff, Bl + gnc * ldB + gkc, nb);
        }
    }
}

__global__ void __launch_bounds__(256)
gemm_bf16_kernel(const bf16* __restrict__ Ah, const bf16* __restrict__ Al,
                 const bf16* __restrict__ Bh, const bf16* __restrict__ Bl,
                 const float* __restrict__ bias, float* __restrict__ C,
                 int M, int N, int K, int act, const int* __restrict__ Mdev,
                 int ldA, int ldB)
{
    if (Mdev) {
        M = min(M, *Mdev);
        if ((long)blockIdx.y * 128 >= (long)M) return;
    }
    extern __shared__ __align__(16) bf16 dsm[];
    unsigned sbase = (unsigned)__cvta_generic_to_shared(dsm);

    int tid = threadIdx.x;
    int warp = tid >> 5, lane = tid & 31;
    int wm = (warp & 1) * 64;
    int wn = (warp >> 1) * 32;
    long row0 = (long)blockIdx.y * 128;
    long col0 = (long)blockIdx.x * 128;

    float acc[4][4][4];
#pragma unroll
    for (int a = 0; a < 4; a++)
#pragma unroll
        for (int b = 0; b < 4; b++)
#pragma unroll
            for (int c = 0; c < 4; c++) acc[a][b][c] = 0.f;

    int am_r = (lane & 7) + ((lane >> 3) & 1) * 8;
    int a_c8 = ((lane >> 4) & 1) * 8;
    int b_r  = (lane & 7) + ((lane >> 4) & 1) * 8;
    int b_c8 = ((lane >> 3) & 1) * 8;

    int T = (K + 31) / 32;

#pragma unroll
    for (int kt = 0; kt < GSTG; kt++) {
        gbf_prefetch(Ah, Al, Bh, Bl, row0, col0, M, N, K, ldA, ldB, kt, T, sbase, kt, tid);
        asm volatile("cp.async.commit_group;\n");
    }

    for (int kt = 0; kt < T; kt++) {
        asm volatile("cp.async.wait_group %0;\n" :: "n"(GSTG - 1));
        __syncthreads();

        int stg = kt % GSTG;
        unsigned sst = sbase + (unsigned)stg * STAGE_B;
        unsigned aB = sst;
        unsigned bB = sst + 2 * PLANE_B;

#pragma unroll
        for (int ks = 0; ks < 2; ks++) {
            int kb = ks * 16;
            unsigned bh[2][4], bl[2][4];
#pragma unroll
            for (int pp = 0; pp < 2; pp++) {
                unsigned addr = bB + (unsigned)(((wn + pp * 16 + b_r) * LDSB + kb + b_c8) * 2);
                LDSM4(bh[pp], addr);
                LDSM4(bl[pp], addr + PLANE_B);
            }
            unsigned ahf[4][4], alf[4][4];
#pragma unroll
            for (int mi = 0; mi < 4; mi++) {
                unsigned addr = aB + (unsigned)(((wm + mi * 16 + am_r) * LDSB + kb + a_c8) * 2);
                LDSM4(ahf[mi], addr);
                LDSM4(alf[mi], addr + PLANE_B);
            }
#pragma unroll
            for (int mi = 0; mi < 4; mi++)
#pragma unroll
                for (int ni = 0; ni < 4; ni++)
                    MMA_BF16(acc[mi][ni], ahf[mi], (&bh[ni >> 1][(ni & 1) * 2]));
#pragma unroll
            for (int mi = 0; mi < 4; mi++)
#pragma unroll
                for (int ni = 0; ni < 4; ni++)
                    MMA_BF16(acc[mi][ni], ahf[mi], (&bl[ni >> 1][(ni & 1) * 2]));
#pragma unroll
            for (int mi = 0; mi < 4; mi++)
#pragma unroll
                for (int ni = 0; ni < 4; ni++)
                    MMA_BF16(acc[mi][ni], alf[mi], (&bh[ni >> 1][(ni & 1) * 2]));
        }
        __syncthreads();
        gbf_prefetch(Ah, Al, Bh, Bl, row0, col0, M, N, K, ldA, ldB, kt + GSTG, T, sbase, stg, tid);
        asm volatile("cp.async.commit_group;\n");
    }

#pragma unroll
    for (int mi = 0; mi < 4; mi++) {
#pragma unroll
        for (int ni = 0; ni < 4; ni++) {
            long r = row0 + wm + mi * 16 + (lane >> 2);
            long c = col0 + wn + ni * 8 + (lane & 3) * 2;
#pragma unroll
            for (int half = 0; half < 2; half++) {
                long rr = r + half * 8;
                if (rr >= M) continue;
#pragma unroll
                for (int e = 0; e < 2; e++) {
                    long cc = c + e;
                    if (cc >= N) continue;
                    float v = acc[mi][ni][half * 2 + e];
                    if (bias) v += bias[cc];
                    if (act == 1) v = fmaxf(v, 0.f);
                    C[(size_t)rr * N + cc] = v;
                }
            }
        }
    }
}

static void gemm_bf16(const bf16* Ah, const bf16* Al, const bf16* Bh, const bf16* Bl,
                      const float* bias, float* C, int M, int N, int K, int act,
                      const int* Mdev = nullptr, int ldA = 0, int ldB = 0,
                      cudaStream_t st = 0)
{
    static int attr_done = 0;
    if (!attr_done) {
        cudaFuncSetAttribute(gemm_bf16_kernel,
                             cudaFuncAttributeMaxDynamicSharedMemorySize, GSTG * STAGE_B);
        attr_done = 1;
    }
    if (ldA == 0) ldA = K;
    if (ldB == 0) ldB = K;
    dim3 grid((N + 127) / 128, (M + 127) / 128);
    gemm_bf16_kernel<<<grid, 256, GSTG * STAGE_B, st>>>(Ah, Al, Bh, Bl, bias, C, M, N, K, act, Mdev, ldA, ldB);
}

// ================= conversion kernels =================
__device__ __forceinline__ void split1(float f, bf16& h, bf16& l)
{
    h = __float2bfloat16(f);
    l = __float2bfloat16(f - __bfloat162float(h));
}

__global__ void split_kernel(const float* __restrict__ x, bf16* __restrict__ hi,
                             bf16* __restrict__ lo, size_t n4)
{
    size_t i = (size_t)blockIdx.x * blockDim.x + threadIdx.x;
    if (i >= n4) return;
    float4 f = ((const float4*)x)[i];
    bf16 h0, l0, h1, l1, h2, l2, h3, l3;
    split1(f.x, h0, l0); split1(f.y, h1, l1); split1(f.z, h2, l2); split1(f.w, h3, l3);
    bf162 vh0; vh0.x = h0; vh0.y = h1;
    bf162 vh1; vh1.x = h2; vh1.y = h3;
    bf162 vl0; vl0.x = l0; vl0.y = l1;
    bf162 vl1; vl1.x = l2; vl1.y = l3;
    ((bf162*)hi)[i * 2] = vh0; ((bf162*)hi)[i * 2 + 1] = vh1;
    ((bf162*)lo)[i * 2] = vl0; ((bf162*)lo)[i * 2 + 1] = vl1;
}

static void split(const float* x, bf16* hi, bf16* lo, size_t n, cudaStream_t st = 0)
{
    size_t n4 = n / 4;
    split_kernel<<<(unsigned)((n4 + 255) / 256), 256, 0, st>>>(x, hi, lo, n4);
}

__global__ void transpose_split_kernel(const float* __restrict__ B, bf16* __restrict__ Th,
                                       bf16* __restrict__ Tl, int K, int N)
{
    __shared__ float tile[32][33];
    int k0 = blockIdx.y * 32, n0 = blockIdx.x * 32;
    int tx = threadIdx.x, ty = threadIdx.y;  // 32 x 8
#pragma unroll
    for (int i = 0; i < 32; i += 8) {
        int k = k0 + ty + i, n = n0 + tx;
        tile[ty + i][tx] = (k < K && n < N) ? B[(size_t)k * N + n] : 0.f;
    }
    __syncthreads();
#pragma unroll
    for (int i = 0; i < 32; i += 8) {
        int n = n0 + ty + i, k = k0 + tx;
        if (n < N && k < K) {
            float f = tile[tx][ty + i];
            bf16 h, l; split1(f, h, l);
            Th[(size_t)n * K + k] = h;
            Tl[(size_t)n * K + k] = l;
        }
    }
}

// ---------------- fast activations ----------------
__device__ __forceinline__ float fsig(float x)
{
    return __fdividef(1.f, 1.f + __expf(-x));
}
__device__ __forceinline__ float ftanh(float x)
{
    x = fminf(fmaxf(x, -15.f), 15.f);
    float e = __expf(-2.f * x);
    return __fdividef(1.f - e, 1.f + e);
}

// ---------------- length-compaction permutation ----------------
__global__ void build_perm_kernel(const int* __restrict__ lens)
{
    __shared__ int slens[Mlstm];
    __shared__ int bins[Lq + 1];
    __shared__ int offs[Lq + 1];
    int tid = threadIdx.x;
    if (tid <= Lq) bins[tid] = 0;
    __syncthreads();
    for (int i = tid; i < Mlstm; i += blockDim.x) {
        int l = lens[i];
        slens[i] = l;
        atomicAdd(&bins[l], 1);
    }
    __syncthreads();
    if (tid == 0) {
        int off = 0;
        for (int l = Lq; l >= 0; l--) { offs[l] = off; off += bins[l]; }
        int c = 0;
        for (int t = Lq - 1; t >= 0; t--) { c += bins[t + 1]; g_cnt[t] = c; }
        int cur[Lq + 1];
        for (int l = 0; l <= Lq; l++) cur[l] = offs[l];
        for (int i = 0; i < Mlstm; i++) {
            int l = slens[i];
            g_perm[cur[l]++] = i;
        }
        for (int i = 0; i < Mlstm; i++) g_iperm[g_perm[i]] = i;
    }
}

// ---------------- small custom kernels ----------------
__global__ void build_enc_kernel(const float* __restrict__ eo, const int* __restrict__ etype,
                                 const int* __restrict__ eid, const float* __restrict__ temb,
                                 const float* __restrict__ iemb, float* __restrict__ enc)
{
    int bs = blockIdx.x;
    const float* src = eo + (long)bs * HBq;
    float* dst = enc + (long)bs * D0q;
    int ty = etype[bs], idv = eid[bs];
    for (int j = threadIdx.x; j < D0q; j += blockDim.x) {
        float v;
        if (j < HBq)            v = src[j];
        else if (j < HBq + DTq) v = temb[ty * DTq + (j - HBq)];
        else                    v = iemb[idv * DIq + (j - HBq - DTq)];
        dst[j] = v;
    }
}

__global__ void softmax256_kernel(float* __restrict__ x)
{
    int row = blockIdx.x;
    int tid = threadIdx.x;
    float v = x[(long)row * 256 + tid];
    __shared__ float red[8];
    int lane = tid & 31, warp = tid >> 5;
    float m = v;
#pragma unroll
    for (int o = 16; o > 0; o >>= 1) m = fmaxf(m, __shfl_xor_sync(0xffffffffu, m, o));
    if (lane == 0) red[warp] = m;
    __syncthreads();
    if (tid == 0) {
        float mm = red[0];
        for (int w = 1; w < 8; w++) mm = fmaxf(mm, red[w]);
        red[0] = mm;
    }
    __syncthreads();
    float mx = red[0];
    float e = expf(v - mx);
    float s = e;
#pragma unroll
    for (int o = 16; o > 0; o >>= 1) s += __shfl_xor_sync(0xffffffffu, s, o);
    __shared__ float red2[8];
    if (lane == 0) red2[warp] = s;
    __syncthreads();
    if (tid == 0) {
        float ss = 0.f;
        for (int w = 0; w < 8; w++) ss += red2[w];
        red2[0] = ss;
    }
    __syncthreads();
    x[(long)row * 256 + tid] = e / red2[0];
}

__global__ void gather_ih_l0_kernel(const float* __restrict__ proj, const int* __restrict__ nodes,
                                    float* __restrict__ ih)
{
    int r = blockIdx.x;
    int t = 1 + r / Mlstm, i = r % Mlstm;
    if (i >= g_cnt[t]) return;
    int orig = g_perm[i];
    int b = orig / (Pq * Kq);
    int node = nodes[orig * Lq + t];
    const float4* src = (const float4*)(proj + ((size_t)(b * Nq + node)) * BANK4q);
    float4* dst = (float4*)(ih + ((size_t)t * Mlstm + i) * BANK4q);
    for (int j = threadIdx.x; j < BANK4q / 4; j += blockDim.x) dst[j] = src[j];
}

__global__ void gather_w64_kernel(const float* __restrict__ src, const int* __restrict__ nodes,
                                  float* __restrict__ dst, int cslot)
{
    int i = blockIdx.x;
    if (i >= g_cnt[cslot]) return;
    int orig = g_perm[i];
    int b = orig / (Pq * Kq);
    int node = nodes[orig * Lq];
    const float4* s = (const float4*)(src + ((size_t)(b * Nq + node)) * BANK4q);
    float4* d = (float4*)(dst + (size_t)i * BANK4q);
    for (int j = threadIdx.x; j < BANK4q / 4; j += blockDim.x) d[j] = s[j];
}

__global__ void cand_cell_kernel(const float* __restrict__ proj, float* __restrict__ ccand,
                                 bf16* __restrict__ hch, bf16* __restrict__ hcl)
{
    int i = blockIdx.y;
    int j = blockIdx.x * blockDim.x + threadIdx.x;
    if (j >= BANKq) return;
    const float* g = proj + (size_t)i * BANK4q;
    float gi = g[j], gg = g[2 * BANKq + j], go = g[3 * BANKq + j];
    float cn = fsig(gi) * ftanh(gg);
    float hn = fsig(go) * ftanh(cn);
    ccand[(size_t)i * BANKq + j] = cn;
    bf16 h, l; split1(hn, h, l);
    hch[(size_t)i * BANKq + j] = h;
    hcl[(size_t)i * BANKq + j] = l;
}

__global__ void gather0_kernel(const bf16* __restrict__ hch, const bf16* __restrict__ hcl,
                               const float* __restrict__ ccand, const int* __restrict__ nodes,
                               bf16* __restrict__ sh, bf16* __restrict__ sl,
                               float* __restrict__ c,
                               bf16* __restrict__ seq_hi, bf16* __restrict__ seq_lo,
                               float* __restrict__ hs)
{
    int i = blockIdx.x;
    int orig = g_perm[i];
    int b = orig / (Pq * Kq);
    size_t idx = ((size_t)(b * Nq + nodes[orig * Lq])) * BANKq;
    size_t dst = (size_t)i * BANKq;
    for (int j = threadIdx.x; j < BANKq; j += blockDim.x) {
        bf16 h = hch[idx + j], l = hcl[idx + j];
        sh[dst + j] = h;
        sl[dst + j] = l;
        c[dst + j] = ccand[idx + j];
        if (seq_hi) { seq_hi[dst + j] = h; seq_lo[dst + j] = l; }
        if (hs) hs[dst + j] = __bfloat162float(h) + __bfloat162float(l);
    }
}

__global__ void lstm_cell_kernel(const float* __restrict__ ih, const float* __restrict__ hh,
                                 bf16* __restrict__ h_hi, bf16* __restrict__ h_lo,
                                 bf16* __restrict__ seq_hi, bf16* __restrict__ seq_lo,
                                 float* __restrict__ c, float* __restrict__ hs, int t)
{
    int i = blockIdx.y;
    if (i >= g_cnt[t]) return;
    int j = blockIdx.x * blockDim.x + threadIdx.x;
    if (j >= BANKq) return;
    const float* g = ih + ((size_t)t * Mlstm + i) * BANK4q;
    const float* hr = hh + (size_t)i * BANK4q;
    float gi = g[j] + hr[j];
    float gf = g[BANKq + j] + hr[BANKq + j];
    float gg = g[2 * BANKq + j] + hr[2 * BANKq + j];
    float go = g[3 * BANKq + j] + hr[3 * BANKq + j];
    float cp = c[(size_t)i * BANKq + j];
    float cn = fsig(gf) * cp + fsig(gi) * ftanh(gg);
    float hn = fsig(go) * ftanh(cn);
    c[(size_t)i * BANKq + j] = cn;
    bf16 h, l; split1(hn, h, l);
    h_hi[(size_t)i * BANKq + j] = h;
    h_lo[(size_t)i * BANKq + j] = l;
    if (seq_hi) {
        seq_hi[((size_t)t * Mlstm + i) * BANKq + j] = h;
        seq_lo[((size_t)t * Mlstm + i) * BANKq + j] = l;
    }
    if (hs) hs[((size_t)t * Mlstm + i) * BANKq + j] = hn;
}

__global__ void maxpool_split_kernel(const float* __restrict__ hs, const int* __restrict__ lens,
                                     bf16* __restrict__ hi, bf16* __restrict__ lo)
{
    int i = blockIdx.y;
    int j = blockIdx.x * blockDim.x + threadIdx.x;
    if (j >= BANKq) return;
    int orig = g_perm[i];
    int len = lens[orig];
    float m = -1e9f;
    const float* base = hs + (size_t)i * BANKq + j;
    for (int t = 0; t < Lq; t++)
        if (t < len) m = fmaxf(m, base[(size_t)t * Mlstm * BANKq]);
    float r = (len > 0) ? m : 0.f;
    bf16 h, l; split1(r, h, l);
    hi[(size_t)i * BANKq + j] = h;
    lo[(size_t)i * BANKq + j] = l;
}

__global__ void zero_kv_tail_kernel(float* __restrict__ kb, float* __restrict__ vb)
{
    int i = blockIdx.x;
    if (i < g_cnt[0]) return;
    float4* k4 = (float4*)(kb + (size_t)i * BANKq);
    float4* v4 = (float4*)(vb + (size_t)i * BANKq);
    float4 z = {0.f, 0.f, 0.f, 0.f};
    for (int j = threadIdx.x; j < BANKq / 4; j += blockDim.x) { k4[j] = z; v4[j] = z; }
}

__global__ void gather_ht_kernel(const float* __restrict__ feats, const int* __restrict__ htp,
                                 float* __restrict__ hf, float* __restrict__ tf,
                                 bf16* __restrict__ qh, bf16* __restrict__ ql)
{
    int bp = blockIdx.x;
    int b = bp / Pq;
    int h0 = htp[bp * 2 + 0], t0 = htp[bp * 2 + 1];
    h0 = (h0 == 0) ? 0 : h0 - 1;
    t0 = (t0 == 0) ? 0 : t0 - 1;
    const float* hsrc = feats + ((size_t)b * Nq + (Nq - Eq) + h0) * BANKq;
    const float* tsrc = feats + ((size_t)b * Nq + (Nq - Eq) + t0) * BANKq;
    for (int j = threadIdx.x; j < BANKq; j += blockDim.x) {
        float hv = hsrc[j], tv = tsrc[j];
        hf[(size_t)bp * BANKq + j] = hv;
        tf[(size_t)bp * BANKq + j] = tv;
        bf16 h, l; split1(hv - tv, h, l);
        qh[(size_t)bp * BANKq + j] = h;
        ql[(size_t)bp * BANKq + j] = l;
    }
}

__global__ void mha_attn_kernel(const float* __restrict__ q, const float* __restrict__ k,
                                const float* __restrict__ v, const int* __restrict__ plens,
                                const float* __restrict__ rmask,
                                bf16* __restrict__ ctx_hi, bf16* __restrict__ ctx_lo,
                                int* __restrict__ validany)
{
    int bp = blockIdx.x;
    int tid = threadIdx.x;
    int warp = tid >> 5, lane = tid & 31;
    __shared__ float sc[NHq][Kq];
    __shared__ float aw[NHq][Kq];
    __shared__ int vm[Kq];
    __shared__ int slot[Kq];
    if (tid < Kq) {
        vm[tid] = (rmask[bp] > 0.f && plens[bp * Kq + tid] > 0) ? 1 : 0;
        slot[tid] = g_iperm[bp * Kq + tid];
    }
    __syncthreads();
    {
        int h = warp / Kq, kk = warp % Kq;
        const float* qh = q + (size_t)bp * BANKq + h * DHq;
        const float* kh = k + (size_t)slot[kk] * BANKq + h * DHq;
        float s = 0.f;
        for (int d = lane; d < DHq; d += 32) s += qh[d] * kh[d];
#pragma unroll
        for (int o = 16; o > 0; o >>= 1) s += __shfl_xor_sync(0xffffffffu, s, o);
        if (lane == 0) {
            s = s / sqrtf((float)DHq);
            sc[h][kk] = vm[kk] ? s : -1e9f;
        }
    }
    __syncthreads();
    if (tid < NHq) {
        int h = tid;
        float m = fmaxf(fmaxf(sc[h][0], sc[h][1]), sc[h][2]);
        float e0 = expf(sc[h][0] - m), e1 = expf(sc[h][1] - m), e2 = expf(sc[h][2] - m);
        float s = e0 + e1 + e2;
        aw[h][0] = e0 / s; aw[h][1] = e1 / s; aw[h][2] = e2 / s;
    }
    if (tid == 0) validany[bp] = (vm[0] | vm[1] | vm[2]);
    __syncthreads();
    const float* v0 = v + (size_t)slot[0] * BANKq;
    const float* v1 = v + (size_t)slot[1] * BANKq;
    const float* v2 = v + (size_t)slot[2] * BANKq;
    for (int j = tid; j < BANKq; j += blockDim.x) {
        int h = j / DHq;
        float r = aw[h][0] * v0[j] + aw[h][1] * v1[j] + aw[h][2] * v2[j];
        bf16 hh2, ll2; split1(r, hh2, ll2);
        ctx_hi[(size_t)bp * BANKq + j] = hh2;
        ctx_lo[(size_t)bp * BANKq + j] = ll2;
    }
}

// bank rows -> split bf16 (168 rows)
__global__ void bank_split_kernel(const float* __restrict__ feats,
                                  bf16* __restrict__ bh, bf16* __restrict__ bl)
{
    int i = blockIdx.x;
    int b = i / Eq, e = i % Eq;
    const float* src = feats + ((size_t)b * Nq + (Nq - Eq) + e) * BANKq;
    size_t dst = (size_t)i * BANKq;
    for (int j = threadIdx.x; j < BANKq; j += blockDim.x) {
        bf16 h, l; split1(src[j], h, l);
        bh[dst + j] = h;
        bl[dst + j] = l;
    }
}

// of_rest = [abs, prod, pinfo] (1024 x 4728) split bf16
__global__ void build_of_rest_kernel(const float* __restrict__ hf, const float* __restrict__ tf,
                                     const float* __restrict__ pinfo, const int* __restrict__ validany,
                                     bf16* __restrict__ oh, bf16* __restrict__ ol)
{
    int bp = blockIdx.x;
    int va = validany[bp];
    const float* hr = hf + (size_t)bp * BANKq;
    const float* tr = tf + (size_t)bp * BANKq;
    const float* pr = pinfo + (size_t)bp * BANKq;
    size_t base = (size_t)bp * BANK3q;
    for (int j = threadIdx.x; j < BANK3q; j += blockDim.x) {
        int seg = j / BANKq, jj = j - seg * BANKq;
        float v;
        if (seg == 0)      v = fabsf(hr[jj] - tr[jj]);
        else if (seg == 1) v = hr[jj] * tr[jj];
        else               v = va ? pr[jj] : 0.f;
        bf16 h, l; split1(v, h, l);
        oh[base + j] = h;
        ol[base + j] = l;
    }
}

// hid[r] = relu(hid[r] + p1[bank(h_r)] + p2[bank(t_r)])
__global__ void combine_pred_kernel(float* __restrict__ hid, const float* __restrict__ p1,
                                    const float* __restrict__ p2, const int* __restrict__ htp)
{
    int r = blockIdx.x;
    int b = r / Pq;
    int h0 = htp[r * 2 + 0], t0 = htp[r * 2 + 1];
    h0 = (h0 == 0) ? 0 : h0 - 1;
    t0 = (t0 == 0) ? 0 : t0 - 1;
    const float* q1 = p1 + (size_t)(b * Eq + h0) * BANK5q;
    const float* q2 = p2 + (size_t)(b * Eq + t0) * BANK5q;
    float* hr = hid + (size_t)r * BANK5q;
    for (int j = threadIdx.x; j < BANK5q; j += blockDim.x)
        hr[j] = fmaxf(hr[j] + q1[j] + q2[j], 0.f);
}

// small head for the N=2 output
__global__ void __launch_bounds__(256)
head2_kernel(const float* __restrict__ hid, const float* __restrict__ bW,
             const float* __restrict__ bb, float* __restrict__ out2)
{
    int m = blockIdx.x;
    int tid = threadIdx.x, lane = tid & 31, warp = tid >> 5;
    const float* hr = hid + (size_t)m * BANK5q;
    float a0 = 0.f, a1 = 0.f;
    for (int k = tid; k < BANK5q; k += 256) {
        float h = hr[k];
        a0 = fmaf(h, bW[(size_t)k * 2], a0);
        a1 = fmaf(h, bW[(size_t)k * 2 + 1], a1);
    }
#pragma unroll
    for (int o = 16; o > 0; o >>= 1) {
        a0 += __shfl_xor_sync(0xffffffffu, a0, o);
        a1 += __shfl_xor_sync(0xffffffffu, a1, o);
    }
    __shared__ float r0[8], r1[8];
    if (lane == 0) { r0[warp] = a0; r1[warp] = a1; }
    __syncthreads();
    if (tid == 0) {
        float s0 = 0.f, s1 = 0.f;
        for (int w = 0; w < 8; w++) { s0 += r0[w]; s1 += r1[w]; }
        out2[(size_t)m * 2 + 0] = s0 + bb[0];
        out2[(size_t)m * 2 + 1] = s1 + bb[1];
    }
}

// ---------------- orchestration ----------------
extern "C" void kernel_launch(void* const* d_in, const int* in_sizes, int n_in,
                              void* d_out, int out_size)
{
    const float* encoder_outputs = (const float*)d_in[0];
    const int*   entity_type     = (const int*)  d_in[1];
    const int*   entity_id       = (const int*)  d_in[2];
    const float* sub2words       = (const float*)d_in[3];
    const float* adj             = (const float*)d_in[4];
    const int*   h_t_pairs       = (const int*)  d_in[5];
    const float* rel_mask        = (const float*)d_in[6];
    const int*   path_nodes      = (const int*)  d_in[7];
    const int*   path_lens       = (const int*)  d_in[8];
    const float* type_emb        = (const float*)d_in[9];
    const float* id_emb          = (const float*)d_in[10];
    const float* gcn0_W          = (const float*)d_in[11];
    const float* gcn0_b          = (const float*)d_in[12];
    const float* gcn_W           = (const float*)d_in[13];
    const float* gcn_b           = (const float*)d_in[14];
    const float* attn_Wq         = (const float*)d_in[15];
    const float* attn_Wk         = (const float*)d_in[16];
    const float* attn_Wv         = (const float*)d_in[17];
    const float* lstm_Wih        = (const float*)d_in[18];
    const float* lstm_Whh        = (const float*)d_in[19];
    const float* lstm_b          = (const float*)d_in[20];
    const float* mha_inW         = (const float*)d_in[21];
    const float* mha_inb         = (const float*)d_in[22];
    const float* mha_outW        = (const float*)d_in[23];
    const float* mha_outb        = (const float*)d_in[24];
    const float* pred_W          = (const float*)d_in[25];
    const float* pred_b          = (const float*)d_in[26];
    const float* mW              = (const float*)d_in[27];
    const float* mb              = (const float*)d_in[28];
    const float* bW              = (const float*)d_in[29];
    const float* bb              = (const float*)d_in[30];
    float* out = (float*)d_out;

    void* p;
#define SYMF(var, sym) cudaGetSymbolAddress(&p, sym); float* var = (float*)p;
#define SYMB(var, sym) cudaGetSymbolAddress(&p, sym); bf16* var = (bf16*)p;
    SYMF(enc,   g_enc);    SYMF(feats, g_feats);  SYMF(tmp,   g_tmp);
    SYMF(x1,    g_x1);     SYMF(xq,    g_xq);     SYMF(xk,    g_xk);
    SYMF(xv,    g_xv);     SYMF(att,   g_att);
    SYMF(ih,    g_ih);     SYMF(hh,    g_hh);
    SYMF(cbuf,  g_c);      SYMF(hs1,   g_hs1);
    SYMF(hf,    g_hf);     SYMF(tf,    g_tf);
    SYMF(qb,    g_q);      SYMF(ccand, g_ccand);
    SYMF(kb,    g_k);      SYMF(vb,    g_v);
    SYMF(pinfo, g_pinfo);  SYMF(pp,    g_pp);     SYMF(hid,   g_hid);
    SYMB(ah,  g_ah);  SYMB(al,  g_al);
    SYMB(sh,  g_sh);  SYMB(sl,  g_sl);
    SYMB(hch, g_hch); SYMB(hcl, g_hcl);
    SYMB(q2h, g_q2h); SYMB(q2l, g_q2l);
    SYMB(bkh, g_bkh); SYMB(bkl, g_bkl);
    SYMB(w1h, g_w1h); SYMB(w1l, g_w1l);
    SYMB(w2h, g_w2h); SYMB(w2l, g_w2l);
    SYMB(w3h, g_w3h); SYMB(w3l, g_w3l);
    SYMB(w4h, g_w4h); SYMB(w4l, g_w4l);
    SYMB(mwh, g_mwh); SYMB(mwl, g_mwl);
    SYMB(owh, g_owh); SYMB(owl, g_owl);
    SYMB(wph, g_wph); SYMB(wpl, g_wpl);
    cudaGetSymbolAddress(&p, g_validany); int* validany = (int*)p;
    cudaGetSymbolAddress(&p, g_cnt);      int* cntdev = (int*)p;
#undef SYMF
#undef SYMB

    // ---- persistent side stream + events ----
    static cudaStream_t s2 = nullptr;
    static cudaEvent_t evFork = nullptr, evW0 = nullptr, evW1 = nullptr,
                       evFeats = nullptr, evSide = nullptr;
    static cudaEvent_t evX[NLq], evX1[NLq], evQl[NLq];
    if (!s2) {
        cudaStreamCreateWithFlags(&s2, cudaStreamNonBlocking);
        cudaEventCreateWithFlags(&evFork,  cudaEventDisableTiming);
        cudaEventCreateWithFlags(&evW0,    cudaEventDisableTiming);
        cudaEventCreateWithFlags(&evW1,    cudaEventDisableTiming);
        cudaEventCreateWithFlags(&evFeats, cudaEventDisableTiming);
        cudaEventCreateWithFlags(&evSide,  cudaEventDisableTiming);
        for (int l = 0; l < NLq; l++) {
            cudaEventCreateWithFlags(&evX[l],  cudaEventDisableTiming);
            cudaEventCreateWithFlags(&evX1[l], cudaEventDisableTiming);
            cudaEventCreateWithFlags(&evQl[l], cudaEventDisableTiming);
        }
    }

    const size_t W4 = (size_t)BANK4q * BANKq;
    int xoff[NLq]   = {808, 1064};
    int outoff[NLq] = {1064, 1320};

    // ======== FORK: side stream: LSTM weight splits (needed earliest) ========
    cudaEventRecord(evFork, 0);
    cudaStreamWaitEvent(s2, evFork, 0);

    split(lstm_Wih,      w1h, w1l, W4, s2);
    split(lstm_Whh,      w2h, w2l, W4, s2);
    cudaEventRecord(evW0, s2);
    split(lstm_Wih + W4, w3h, w3l, W4, s2);
    split(lstm_Whh + W4, w4h, w4l, W4, s2);
    cudaEventRecord(evW1, s2);

    // ======== main stream: perm + enc + GCN prologue ========
    build_perm_kernel<<<1, 1024>>>(path_lens);
    build_enc_kernel<<<Bq * Sq, 256>>>(encoder_outputs, entity_type, entity_id, type_emb, id_emb, enc);

    gemm(false, sub2words, enc, nullptr, nullptr, feats,
         Nq, D0q, Sq, Sq, D0q, BANKq, 0,
         (long)Nq * Sq, (long)Sq * D0q, (long)Nq * BANKq, 0, Bq, 1.f, 0);
    gemm(false, adj, feats, nullptr, nullptr, tmp,
         Nq, D0q, Nq, Nq, BANKq, D0q, 0,
         (long)Nq * Nq, (long)Nq * BANKq, (long)Nq * D0q, 0, Bq, 1.f, 0);
    gemm(false, tmp, gcn0_W, gcn0_b, nullptr, feats + 808,
         Nq, Gq, D0q, D0q, Gq, BANKq, 0,
         (long)Nq * D0q, 0, (long)Nq * BANKq, 0, Bq, 1.f, 0);
    cudaEventRecord(evX[0], 0);       // x for layer 0 ready

    // ======== GCN layers with host-ordered xq/xv offload ========
    for (int l = 0; l < NLq; l++) {
        const float* x = feats + xoff[l];
        // side: xq = x @ Wq[l]   (wait enqueued AFTER evX[l] was recorded: capture-legal)
        cudaStreamWaitEvent(s2, evX[l], 0);
        gemm(false, x, attn_Wq + (long)l * Gq * Gq, nullptr, nullptr, xq,
             Nq, Gq, Gq, BANKq, Gq, Gq, 0,
             (long)Nq * BANKq, 0, (long)Nq * Gq, 0, Bq, 1.f, 0, s2);
        // main: adj @ x -> tmp ; x1 = relu(tmp @ gcn_W + b)
        gemm(false, adj, x, nullptr, nullptr, tmp,
             Nq, Gq, Nq, Nq, BANKq, Gq, 0,
             (long)Nq * Nq, (long)Nq * BANKq, (long)Nq * Gq, 0, Bq, 1.f, 0);
        gemm(false, tmp, gcn_W + (long)l * Gq * Gq, gcn_b + l * Gq, nullptr, x1,
             Nq, Gq, Gq, Gq, Gq, Gq, 0,
             (long)Nq * Gq, 0, (long)Nq * Gq, 0, Bq, 1.f, 1);
        cudaEventRecord(evX1[l], 0);
        // side: xv = x1 @ Wv[l]
        cudaStreamWaitEvent(s2, evX1[l], 0);
        gemm(false, x1, attn_Wv + (long)l * Gq * Gq, nullptr, nullptr, xv,
             Nq, Gq, Gq, Gq, Gq, Gq, 0,
             (long)Nq * Gq, 0, (long)Nq * Gq, 0, Bq, 1.f, 0, s2);
        cudaEventRecord(evQl[l], s2);
        // main: xk = x1 @ Wk[l]
        gemm(false, x1, attn_Wk + (long)l * Gq * Gq, nullptr, nullptr, xk,
             Nq, Gq, Gq, Gq, Gq, Gq, 0,
             (long)Nq * Gq, 0, (long)Nq * Gq, 0, Bq, 1.f, 0);
        cudaStreamWaitEvent(0, evQl[l], 0);   // join xq + xv
        gemm(true, xq, xk, nullptr, nullptr, att,
             Nq, Nq, Gq, Gq, Gq, Nq, 0,
             (long)Nq * Gq, (long)Nq * Gq, (long)Nq * Nq, 0, Bq, 0.0625f, 0);
        softmax256_kernel<<<Bq * Nq, 256>>>(att);
        gemm(false, att, xv, nullptr, x1, feats + outoff[l],
             Nq, Gq, Nq, Nq, Gq, BANKq, Gq,
             (long)Nq * Nq, (long)Nq * Gq, (long)Nq * BANKq, (long)Nq * Gq, Bq, 1.f, 1);
        if (l + 1 < NLq) cudaEventRecord(evX[l + 1], 0);
    }
    cudaEventRecord(evFeats, 0);

    // ======== side stream: remaining weight prep + post-feats work ========
    split(mha_inW,  mwh, mwl, (size_t)3 * BANKq * BANKq, s2);
    split(mha_outW, owh, owl, (size_t)BANKq * BANKq, s2);
    {
        dim3 grid((BANK5q + 31) / 32, (BANK5q + 31) / 32);
        transpose_split_kernel<<<grid, dim3(32, 8), 0, s2>>>(pred_W, wph, wpl, BANK5q, BANK5q);
    }
    cudaStreamWaitEvent(s2, evFeats, 0);
    gather_ht_kernel<<<BPq, 256, 0, s2>>>(feats, h_t_pairs, hf, tf, q2h, q2l);
    gemm_bf16(q2h, q2l, mwh, mwl, mha_inb, qb, BPq, BANKq, BANKq, 0, nullptr, 0, 0, s2);
    bank_split_kernel<<<NBANKROWS, 256, 0, s2>>>(feats, bkh, bkl);
    float* p1 = pp;
    float* p2 = pp + (size_t)NBANKROWS * BANK5q;
    gemm_bf16(bkh, bkl, wph, wpl, nullptr, p1,
              NBANKROWS, BANK5q, BANKq, 0, nullptr, BANKq, BANK5q, s2);
    gemm_bf16(bkh, bkl, wph + BANKq, wpl + BANKq, nullptr, p2,
              NBANKROWS, BANK5q, BANKq, 0, nullptr, BANKq, BANK5q, s2);
    cudaEventRecord(evSide, s2);

    // ======== main stream: LSTM ========
    dim3 cg((BANKq + 255) / 256, Mlstm);
    dim3 cg1((BANKq + 255) / 256, BPq);

    cudaStreamWaitEvent(0, evW0, 0);
    // ----- layer 0 (prefix dedup + length compaction) -----
    {
        const float* b0 = lstm_b;
        split(feats, sh, sl, (size_t)Bq * Nq * BANKq);
        gemm_bf16(sh, sl, w1h, w1l, b0, hh, BPq, BANK4q, BANKq, 0);
        gather_ih_l0_kernel<<<3 * Mlstm, 256>>>(hh, path_nodes, ih);
        cand_cell_kernel<<<cg1, 256>>>(hh, ccand, hch, hcl);
        gather0_kernel<<<Mlstm, 256>>>(hch, hcl, ccand, path_nodes, sh, sl, cbuf, ah, al, nullptr);
        gemm_bf16(hch, hcl, w2h, w2l, nullptr, hid, BPq, BANK4q, BANKq, 0);
        gather_w64_kernel<<<Mlstm, 256>>>(hid, path_nodes, hh, 1);
        for (int t = 1; t < Lq; t++) {
            if (t > 1)
                gemm_bf16(sh, sl, w2h, w2l, nullptr, hh, Mlstm, BANK4q, BANKq, 0, cntdev + t);
            lstm_cell_kernel<<<cg, 256>>>(ih, hh, sh, sl, ah, al, cbuf, nullptr, t);
        }
    }

    cudaStreamWaitEvent(0, evW1, 0);
    // ----- layer 1 (same dedup + compaction) -----
    {
        const float* b1 = lstm_b + BANK4q;
        gemm_bf16(hch, hcl, w3h, w3l, b1, hid, BPq, BANK4q, BANKq, 0);
        for (int t = 1; t < Lq; t++)
            gemm_bf16(ah + (size_t)t * Mlstm * BANKq, al + (size_t)t * Mlstm * BANKq,
                      w3h, w3l, b1, ih + (size_t)t * Mlstm * BANK4q,
                      Mlstm, BANK4q, BANKq, 0, cntdev + t);
        cand_cell_kernel<<<cg1, 256>>>(hid, ccand, hch, hcl);
        gather0_kernel<<<Mlstm, 256>>>(hch, hcl, ccand, path_nodes, sh, sl, cbuf,
                                       nullptr, nullptr, hs1);
        gemm_bf16(hch, hcl, w4h, w4l, nullptr, hid, BPq, BANK4q, BANKq, 0);
        gather_w64_kernel<<<Mlstm, 256>>>(hid, path_nodes, hh, 1);
        for (int t = 1; t < Lq; t++) {
            if (t > 1)
                gemm_bf16(sh, sl, w4h, w4l, nullptr, hh, Mlstm, BANK4q, BANKq, 0, cntdev + t);
            lstm_cell_kernel<<<cg, 256>>>(ih, hh, sh, sl, nullptr, nullptr, cbuf, hs1, t);
        }
    }

    // 8) masked max-pool -> pe in COMPACTED order (split bf16 into ah/al)
    maxpool_split_kernel<<<cg, 256>>>(hs1, path_lens, ah, al);

    // ======== JOIN side stream ========
    cudaStreamWaitEvent(0, evSide, 0);

    // 10-11) k/v projections (compacted + count-limited; tail rows zeroed)
    gemm_bf16(ah, al, mwh + (size_t)BANKq * BANKq, mwl + (size_t)BANKq * BANKq,
              mha_inb + BANKq, kb, Mlstm, BANKq, BANKq, 0, cntdev + 0);
    gemm_bf16(ah, al, mwh + 2 * (size_t)BANKq * BANKq, mwl + 2 * (size_t)BANKq * BANKq,
              mha_inb + 2 * BANKq, vb, Mlstm, BANKq, BANKq, 0, cntdev + 0);
    zero_kv_tail_kernel<<<Mlstm, 256>>>(kb, vb);

    // 12) tiny attention over K=3 paths (ctx split into sh/sl)
    mha_attn_kernel<<<BPq, 384>>>(qb, kb, vb, path_lens, rel_mask, sh, sl, validany);

    // 13) pinfo
    gemm_bf16(sh, sl, owh, owl, mha_outb, pinfo, BPq, BANKq, BANKq, 0);

    // 14-15) pred GEMM with segment dedup (partials from side stream)
    build_of_rest_kernel<<<BPq, 256>>>(hf, tf, pinfo, validany, ah, al);
    gemm_bf16(ah, al, wph + 2 * BANKq, wpl + 2 * BANKq, pred_b, hid,
              BPq, BANK5q, BANK3q, 0, nullptr, BANK3q, BANK5q);
    combine_pred_kernel<<<BPq, 256>>>(hid, p1, p2, h_t_pairs);

    // 16) output heads
    gemm(false, hid, mW, mb, nullptr, out,
         BPq, Rq, BANK5q, BANK5q, Rq, Rq, 0, 0, 0, 0, 0, 1, 1.f, 0);
    head2_kernel<<<BPq, 256>>>(hid, bW, bb, out + (size_t)BPq * Rq);
}